// round 1
// baseline (speedup 1.0000x reference)
#include <cuda_runtime.h>
#include <math.h>

#define BATCH 4
#define CH    256
#define NPIX  4096
#define NG    32
#define CPG   8
#define SCALE 0.0625f   // C^-0.5 = 1/16

// ---------------- scratch (device globals: allocation-free) ----------------
__device__ float g_h  [BATCH * CH * NPIX];       // 16 MB groupnorm output [b][c][n]
__device__ float g_qkv[BATCH * 3 * CH * NPIX];   // 48 MB qkv [b][3c][n]
__device__ float g_o  [BATCH * CH * NPIX];       // 16 MB attention out [b][c][n]

// ---------------- GroupNorm ----------------
__global__ void __launch_bounds__(256) gn_kernel(const float* __restrict__ x,
                                                 const float* __restrict__ w,
                                                 const float* __restrict__ bias) {
    const int bg = blockIdx.x;          // 0..127
    const int b = bg >> 5, g = bg & 31;
    const float* xp = x   + (b * CH + g * CPG) * NPIX;
    float*       hp = g_h + (b * CH + g * CPG) * NPIX;
    const int NE = CPG * NPIX;          // 32768 elems (contiguous)

    float s = 0.f, ss = 0.f;
    const float4* x4 = (const float4*)xp;
    for (int i = threadIdx.x; i < NE / 4; i += blockDim.x) {
        float4 v = x4[i];
        s  += v.x + v.y + v.z + v.w;
        ss += v.x * v.x + v.y * v.y + v.z * v.z + v.w * v.w;
    }
    __shared__ float rs[32], rss[32];
    #pragma unroll
    for (int o = 16; o; o >>= 1) {
        s  += __shfl_xor_sync(0xffffffffu, s,  o);
        ss += __shfl_xor_sync(0xffffffffu, ss, o);
    }
    const int lane = threadIdx.x & 31, wid = threadIdx.x >> 5;
    if (lane == 0) { rs[wid] = s; rss[wid] = ss; }
    __syncthreads();
    if (wid == 0) {
        s  = (lane < (int)(blockDim.x >> 5)) ? rs[lane]  : 0.f;
        ss = (lane < (int)(blockDim.x >> 5)) ? rss[lane] : 0.f;
        #pragma unroll
        for (int o = 16; o; o >>= 1) {
            s  += __shfl_xor_sync(0xffffffffu, s,  o);
            ss += __shfl_xor_sync(0xffffffffu, ss, o);
        }
        if (lane == 0) { rs[0] = s; rss[0] = ss; }
    }
    __syncthreads();
    const float mu   = rs[0] / (float)NE;
    const float var  = rss[0] / (float)NE - mu * mu;
    const float rstd = rsqrtf(var + 1e-5f);

    float4* h4 = (float4*)hp;
    for (int i = threadIdx.x; i < NE / 4; i += blockDim.x) {
        const int c = g * CPG + (i >> 10);          // 1024 float4 per channel
        const float wc = w[c] * rstd;
        const float bc = bias[c] - mu * wc;         // (x-mu)*rstd*w + b
        float4 v = x4[i];
        v.x = v.x * wc + bc; v.y = v.y * wc + bc;
        v.z = v.z * wc + bc; v.w = v.w * wc + bc;
        h4[i] = v;
    }
}

// ---------------- 64x64 fp32 GEMM body:  Out[o][n] = sum_c W[o][c]*In[c][n] + bias[o] (+resid) ----------------
__device__ __forceinline__ void gemm64_body(const float* __restrict__ W,
                                            const float* __restrict__ bias,
                                            const float* __restrict__ In,
                                            float* __restrict__ Out,
                                            const float* __restrict__ resid) {
    __shared__ float Ws[16][68];   // [k][o], padded
    __shared__ float Hs[16][64];   // [k][n]
    const int tid = threadIdx.x;
    const int n0 = blockIdx.x * 64;
    const int o0 = blockIdx.y * 64;
    const int tx = tid & 15, ty = tid >> 4;
    const int woo = tid >> 2, wk4 = tid & 3;    // W-load mapping
    const int hkk = tid >> 4, hn4 = tid & 15;   // H-load mapping

    float acc[4][4] = {};
    for (int k0 = 0; k0 < CH; k0 += 16) {
        float4 wv = *(const float4*)(W  + (o0 + woo) * CH   + k0 + 4 * wk4);
        float4 hv = *(const float4*)(In + (k0 + hkk) * NPIX + n0 + 4 * hn4);
        __syncthreads();
        Ws[4 * wk4 + 0][woo] = wv.x; Ws[4 * wk4 + 1][woo] = wv.y;
        Ws[4 * wk4 + 2][woo] = wv.z; Ws[4 * wk4 + 3][woo] = wv.w;
        *(float4*)(&Hs[hkk][4 * hn4]) = hv;
        __syncthreads();
        #pragma unroll
        for (int kk = 0; kk < 16; kk++) {
            float4 a = *(float4*)(&Ws[kk][4 * ty]);
            float4 h = *(float4*)(&Hs[kk][4 * tx]);
            acc[0][0] += a.x * h.x; acc[0][1] += a.x * h.y; acc[0][2] += a.x * h.z; acc[0][3] += a.x * h.w;
            acc[1][0] += a.y * h.x; acc[1][1] += a.y * h.y; acc[1][2] += a.y * h.z; acc[1][3] += a.y * h.w;
            acc[2][0] += a.z * h.x; acc[2][1] += a.z * h.y; acc[2][2] += a.z * h.z; acc[2][3] += a.z * h.w;
            acc[3][0] += a.w * h.x; acc[3][1] += a.w * h.y; acc[3][2] += a.w * h.z; acc[3][3] += a.w * h.w;
        }
    }
    #pragma unroll
    for (int r = 0; r < 4; r++) {
        const int o = o0 + 4 * ty + r;
        const float bs = bias[o];
        const int idx = o * NPIX + n0 + 4 * tx;
        float4 res;
        res.x = acc[r][0] + bs; res.y = acc[r][1] + bs;
        res.z = acc[r][2] + bs; res.w = acc[r][3] + bs;
        if (resid) {
            float4 xv = *(const float4*)(resid + idx);
            res.x += xv.x; res.y += xv.y; res.z += xv.z; res.w += xv.w;
        }
        *(float4*)(Out + idx) = res;
    }
}

__global__ void __launch_bounds__(256) qkv_gemm(const float* __restrict__ W,
                                                const float* __restrict__ bias) {
    const int b = blockIdx.z;
    gemm64_body(W, bias, g_h + b * CH * NPIX, g_qkv + b * 3 * CH * NPIX, nullptr);
}

__global__ void __launch_bounds__(256) proj_gemm(const float* __restrict__ W,
                                                 const float* __restrict__ bias,
                                                 const float* __restrict__ x,
                                                 float* __restrict__ out) {
    const int b = blockIdx.z;
    gemm64_body(W, bias, g_o + b * CH * NPIX, out + b * CH * NPIX, x + b * CH * NPIX);
}

// ---------------- Flash attention, fp32, BM=BN=64 ----------------
// smem: Qs[256][64] | Ks[256][64] | Vs[256][68] | Pst[64][68]  = 218112 B
__global__ void __launch_bounds__(256, 1) attn_kernel() {
    extern __shared__ float sm[];
    float* Qs  = sm;                             // [c][row]  pitch 64
    float* Ks  = sm + 256 * 64;                  // [c][col]  pitch 64
    float* Vs  = sm + 2 * 256 * 64;              // [c][col]  pitch 68 (bank pad)
    float* Pst = sm + 2 * 256 * 64 + 256 * 68;   // [col][row] pitch 68

    const int b  = blockIdx.y;
    const int n0 = blockIdx.x * 64;
    const float* Qg = g_qkv + b * 3 * CH * NPIX;
    const float* Kg = Qg + CH * NPIX;
    const float* Vg = Kg + CH * NPIX;

    const int tid = threadIdx.x;
    const int tx = tid & 15, ty = tid >> 4;      // 16x16 thread grid, 4x4 microtile
    const int lj = tid & 15, lc = tid >> 4;      // tile-load mapping

    // Q tile resident for CTA lifetime
    for (int c = lc; c < CH; c += 16)
        *(float4*)(Qs + c * 64 + 4 * lj) = *(const float4*)(Qg + c * NPIX + n0 + 4 * lj);

    float m[4], l[4], o[4][16];
    #pragma unroll
    for (int r = 0; r < 4; r++) {
        m[r] = -INFINITY; l[r] = 0.f;
        #pragma unroll
        for (int i = 0; i < 16; i++) o[r][i] = 0.f;
    }

    for (int t = 0; t < NPIX / 64; t++) {
        const int j0 = t * 64;
        __syncthreads();   // prev PV done reading Vs/Pst
        for (int c = lc; c < CH; c += 16) {
            *(float4*)(Ks + c * 64 + 4 * lj) = *(const float4*)(Kg + c * NPIX + j0 + 4 * lj);
            *(float4*)(Vs + c * 68 + 4 * lj) = *(const float4*)(Vg + c * NPIX + j0 + 4 * lj);
        }
        __syncthreads();

        // S = Q^T K  (rows 4ty+r, cols 4tx+cc)
        float s[4][4];
        #pragma unroll
        for (int r = 0; r < 4; r++)
            #pragma unroll
            for (int cc = 0; cc < 4; cc++) s[r][cc] = 0.f;

        #pragma unroll 8
        for (int c = 0; c < CH; c++) {
            float4 q = *(float4*)(Qs + c * 64 + 4 * ty);
            float4 k = *(float4*)(Ks + c * 64 + 4 * tx);
            s[0][0] += q.x * k.x; s[0][1] += q.x * k.y; s[0][2] += q.x * k.z; s[0][3] += q.x * k.w;
            s[1][0] += q.y * k.x; s[1][1] += q.y * k.y; s[1][2] += q.y * k.z; s[1][3] += q.y * k.w;
            s[2][0] += q.z * k.x; s[2][1] += q.z * k.y; s[2][2] += q.z * k.z; s[2][3] += q.z * k.w;
            s[3][0] += q.w * k.x; s[3][1] += q.w * k.y; s[3][2] += q.w * k.z; s[3][3] += q.w * k.w;
        }

        // online softmax (row stats reduced across 16 tx lanes)
        #pragma unroll
        for (int r = 0; r < 4; r++) {
            #pragma unroll
            for (int cc = 0; cc < 4; cc++) s[r][cc] *= SCALE;
            float mx = fmaxf(fmaxf(s[r][0], s[r][1]), fmaxf(s[r][2], s[r][3]));
            mx = fmaxf(mx, __shfl_xor_sync(0xffffffffu, mx, 8));
            mx = fmaxf(mx, __shfl_xor_sync(0xffffffffu, mx, 4));
            mx = fmaxf(mx, __shfl_xor_sync(0xffffffffu, mx, 2));
            mx = fmaxf(mx, __shfl_xor_sync(0xffffffffu, mx, 1));
            const float nm = fmaxf(m[r], mx);
            const float al = __expf(m[r] - nm);
            float ps = 0.f;
            #pragma unroll
            for (int cc = 0; cc < 4; cc++) {
                s[r][cc] = __expf(s[r][cc] - nm);
                ps += s[r][cc];
            }
            ps += __shfl_xor_sync(0xffffffffu, ps, 8);
            ps += __shfl_xor_sync(0xffffffffu, ps, 4);
            ps += __shfl_xor_sync(0xffffffffu, ps, 2);
            ps += __shfl_xor_sync(0xffffffffu, ps, 1);
            l[r] = l[r] * al + ps;
            m[r] = nm;
            #pragma unroll
            for (int i = 0; i < 16; i++) o[r][i] *= al;
        }

        // write P transposed: Pst[col][row], rows contiguous -> float4
        #pragma unroll
        for (int cc = 0; cc < 4; cc++) {
            float4 pv = make_float4(s[0][cc], s[1][cc], s[2][cc], s[3][cc]);
            *(float4*)(Pst + (4 * tx + cc) * 68 + 4 * ty) = pv;
        }
        __syncthreads();

        // O += P * V   (thread owns rows 4ty+r, channels c = tx + 16*i)
        #pragma unroll 2
        for (int j4 = 0; j4 < 16; j4++) {
            float4 p0 = *(float4*)(Pst + (4 * j4 + 0) * 68 + 4 * ty);
            float4 p1 = *(float4*)(Pst + (4 * j4 + 1) * 68 + 4 * ty);
            float4 p2 = *(float4*)(Pst + (4 * j4 + 2) * 68 + 4 * ty);
            float4 p3 = *(float4*)(Pst + (4 * j4 + 3) * 68 + 4 * ty);
            #pragma unroll
            for (int i = 0; i < 16; i++) {
                float4 v = *(float4*)(Vs + (tx + 16 * i) * 68 + 4 * j4);
                o[0][i] += p0.x * v.x + p1.x * v.y + p2.x * v.z + p3.x * v.w;
                o[1][i] += p0.y * v.x + p1.y * v.y + p2.y * v.z + p3.y * v.w;
                o[2][i] += p0.z * v.x + p1.z * v.y + p2.z * v.z + p3.z * v.w;
                o[3][i] += p0.w * v.x + p1.w * v.y + p2.w * v.z + p3.w * v.w;
            }
        }
    }

    // epilogue: g_o[b][c][n] = O[n][c] / l
    float* Og = g_o + b * CH * NPIX;
    #pragma unroll
    for (int r = 0; r < 4; r++) {
        const float inv = 1.f / l[r];
        #pragma unroll
        for (int i = 0; i < 16; i++)
            Og[(tx + 16 * i) * NPIX + n0 + 4 * ty + r] = o[r][i] * inv;
    }
}

// ---------------- launch ----------------
extern "C" void kernel_launch(void* const* d_in, const int* in_sizes, int n_in,
                              void* d_out, int out_size) {
    const float* x      = (const float*)d_in[0];
    const float* gn_w   = (const float*)d_in[1];
    const float* gn_b   = (const float*)d_in[2];
    const float* qkv_w  = (const float*)d_in[3];
    const float* qkv_b  = (const float*)d_in[4];
    const float* proj_w = (const float*)d_in[5];
    const float* proj_b = (const float*)d_in[6];
    float* out = (float*)d_out;

    gn_kernel<<<BATCH * NG, 256>>>(x, gn_w, gn_b);

    {
        dim3 g(NPIX / 64, (3 * CH) / 64, BATCH);
        qkv_gemm<<<g, 256>>>(qkv_w, qkv_b);
    }
    {
        const size_t smem = (size_t)(2 * 256 * 64 + 256 * 68 + 64 * 68) * sizeof(float); // 218112
        cudaFuncSetAttribute(attn_kernel, cudaFuncAttributeMaxDynamicSharedMemorySize, (int)smem);
        dim3 g(NPIX / 64, BATCH);
        attn_kernel<<<g, 256, smem>>>();
    }
    {
        dim3 g(NPIX / 64, CH / 64, BATCH);
        proj_gemm<<<g, 256>>>(proj_w, proj_b, x, out);
    }
}

// round 2
// speedup vs baseline: 1.0008x; 1.0008x over previous
#include <cuda_runtime.h>
#include <math.h>

#define BATCH 4
#define CH    256
#define NPIX  4096
#define NG    32
#define CPG   8
#define SCALE 0.0625f   // C^-0.5 = 1/16

// ---------------- scratch (device globals: allocation-free) ----------------
__device__ float g_h  [BATCH * CH * NPIX];       // 16 MB groupnorm output [b][c][n]
__device__ float g_qkv[BATCH * 3 * CH * NPIX];   // 48 MB qkv [b][3c][n]
__device__ float g_o  [BATCH * CH * NPIX];       // 16 MB attention out [b][c][n]

// ---------------- GroupNorm ----------------
__global__ void __launch_bounds__(256) gn_kernel(const float* __restrict__ x,
                                                 const float* __restrict__ w,
                                                 const float* __restrict__ bias) {
    const int bg = blockIdx.x;          // 0..127
    const int b = bg >> 5, g = bg & 31;
    const float* xp = x   + (b * CH + g * CPG) * NPIX;
    float*       hp = g_h + (b * CH + g * CPG) * NPIX;
    const int NE = CPG * NPIX;          // 32768 elems (contiguous)

    float s = 0.f, ss = 0.f;
    const float4* x4 = (const float4*)xp;
    for (int i = threadIdx.x; i < NE / 4; i += blockDim.x) {
        float4 v = x4[i];
        s  += v.x + v.y + v.z + v.w;
        ss += v.x * v.x + v.y * v.y + v.z * v.z + v.w * v.w;
    }
    __shared__ float rs[32], rss[32];
    #pragma unroll
    for (int o = 16; o; o >>= 1) {
        s  += __shfl_xor_sync(0xffffffffu, s,  o);
        ss += __shfl_xor_sync(0xffffffffu, ss, o);
    }
    const int lane = threadIdx.x & 31, wid = threadIdx.x >> 5;
    if (lane == 0) { rs[wid] = s; rss[wid] = ss; }
    __syncthreads();
    if (wid == 0) {
        s  = (lane < (int)(blockDim.x >> 5)) ? rs[lane]  : 0.f;
        ss = (lane < (int)(blockDim.x >> 5)) ? rss[lane] : 0.f;
        #pragma unroll
        for (int o = 16; o; o >>= 1) {
            s  += __shfl_xor_sync(0xffffffffu, s,  o);
            ss += __shfl_xor_sync(0xffffffffu, ss, o);
        }
        if (lane == 0) { rs[0] = s; rss[0] = ss; }
    }
    __syncthreads();
    const float mu   = rs[0] / (float)NE;
    const float var  = rss[0] / (float)NE - mu * mu;
    const float rstd = rsqrtf(var + 1e-5f);

    float4* h4 = (float4*)hp;
    for (int i = threadIdx.x; i < NE / 4; i += blockDim.x) {
        const int c = g * CPG + (i >> 10);          // 1024 float4 per channel
        const float wc = w[c] * rstd;
        const float bc = bias[c] - mu * wc;         // (x-mu)*rstd*w + b
        float4 v = x4[i];
        v.x = v.x * wc + bc; v.y = v.y * wc + bc;
        v.z = v.z * wc + bc; v.w = v.w * wc + bc;
        h4[i] = v;
    }
}

// ---------------- 64x64 fp32 GEMM body:  Out[o][n] = sum_c W[o][c]*In[c][n] + bias[o] (+resid) ----------------
__device__ __forceinline__ void gemm64_body(const float* __restrict__ W,
                                            const float* __restrict__ bias,
                                            const float* __restrict__ In,
                                            float* __restrict__ Out,
                                            const float* __restrict__ resid) {
    __shared__ float Ws[16][68];   // [k][o], padded
    __shared__ float Hs[16][64];   // [k][n]
    const int tid = threadIdx.x;
    const int n0 = blockIdx.x * 64;
    const int o0 = blockIdx.y * 64;
    const int tx = tid & 15, ty = tid >> 4;
    const int woo = tid >> 2, wk4 = tid & 3;    // W-load mapping
    const int hkk = tid >> 4, hn4 = tid & 15;   // H-load mapping

    float acc[4][4] = {};
    for (int k0 = 0; k0 < CH; k0 += 16) {
        float4 wv = *(const float4*)(W  + (o0 + woo) * CH   + k0 + 4 * wk4);
        float4 hv = *(const float4*)(In + (k0 + hkk) * NPIX + n0 + 4 * hn4);
        __syncthreads();
        Ws[4 * wk4 + 0][woo] = wv.x; Ws[4 * wk4 + 1][woo] = wv.y;
        Ws[4 * wk4 + 2][woo] = wv.z; Ws[4 * wk4 + 3][woo] = wv.w;
        *(float4*)(&Hs[hkk][4 * hn4]) = hv;
        __syncthreads();
        #pragma unroll
        for (int kk = 0; kk < 16; kk++) {
            float4 a = *(float4*)(&Ws[kk][4 * ty]);
            float4 h = *(float4*)(&Hs[kk][4 * tx]);
            acc[0][0] += a.x * h.x; acc[0][1] += a.x * h.y; acc[0][2] += a.x * h.z; acc[0][3] += a.x * h.w;
            acc[1][0] += a.y * h.x; acc[1][1] += a.y * h.y; acc[1][2] += a.y * h.z; acc[1][3] += a.y * h.w;
            acc[2][0] += a.z * h.x; acc[2][1] += a.z * h.y; acc[2][2] += a.z * h.z; acc[2][3] += a.z * h.w;
            acc[3][0] += a.w * h.x; acc[3][1] += a.w * h.y; acc[3][2] += a.w * h.z; acc[3][3] += a.w * h.w;
        }
    }
    #pragma unroll
    for (int r = 0; r < 4; r++) {
        const int o = o0 + 4 * ty + r;
        const float bs = bias[o];
        const int idx = o * NPIX + n0 + 4 * tx;
        float4 res;
        res.x = acc[r][0] + bs; res.y = acc[r][1] + bs;
        res.z = acc[r][2] + bs; res.w = acc[r][3] + bs;
        if (resid) {
            float4 xv = *(const float4*)(resid + idx);
            res.x += xv.x; res.y += xv.y; res.z += xv.z; res.w += xv.w;
        }
        *(float4*)(Out + idx) = res;
    }
}

__global__ void __launch_bounds__(256) qkv_gemm(const float* __restrict__ W,
                                                const float* __restrict__ bias) {
    const int b = blockIdx.z;
    gemm64_body(W, bias, g_h + b * CH * NPIX, g_qkv + b * 3 * CH * NPIX, nullptr);
}

__global__ void __launch_bounds__(256) proj_gemm(const float* __restrict__ W,
                                                 const float* __restrict__ bias,
                                                 const float* __restrict__ x,
                                                 float* __restrict__ out) {
    const int b = blockIdx.z;
    gemm64_body(W, bias, g_o + b * CH * NPIX, out + b * CH * NPIX, x + b * CH * NPIX);
}

// ---------------- Flash attention, fp32, BM=BN=64 ----------------
// smem: Qs[256][64] | Ks[256][64] | Vs[256][68] | Pst[64][68]  = 218112 B
__global__ void __launch_bounds__(256, 1) attn_kernel() {
    extern __shared__ float sm[];
    float* Qs  = sm;                             // [c][row]  pitch 64
    float* Ks  = sm + 256 * 64;                  // [c][col]  pitch 64
    float* Vs  = sm + 2 * 256 * 64;              // [c][col]  pitch 68 (bank pad)
    float* Pst = sm + 2 * 256 * 64 + 256 * 68;   // [col][row] pitch 68

    const int b  = blockIdx.y;
    const int n0 = blockIdx.x * 64;
    const float* Qg = g_qkv + b * 3 * CH * NPIX;
    const float* Kg = Qg + CH * NPIX;
    const float* Vg = Kg + CH * NPIX;

    const int tid = threadIdx.x;
    const int tx = tid & 15, ty = tid >> 4;      // 16x16 thread grid, 4x4 microtile
    const int lj = tid & 15, lc = tid >> 4;      // tile-load mapping

    // Q tile resident for CTA lifetime
    for (int c = lc; c < CH; c += 16)
        *(float4*)(Qs + c * 64 + 4 * lj) = *(const float4*)(Qg + c * NPIX + n0 + 4 * lj);

    float m[4], l[4], o[4][16];
    #pragma unroll
    for (int r = 0; r < 4; r++) {
        m[r] = -INFINITY; l[r] = 0.f;
        #pragma unroll
        for (int i = 0; i < 16; i++) o[r][i] = 0.f;
    }

    for (int t = 0; t < NPIX / 64; t++) {
        const int j0 = t * 64;
        __syncthreads();   // prev PV done reading Vs/Pst
        for (int c = lc; c < CH; c += 16) {
            *(float4*)(Ks + c * 64 + 4 * lj) = *(const float4*)(Kg + c * NPIX + j0 + 4 * lj);
            *(float4*)(Vs + c * 68 + 4 * lj) = *(const float4*)(Vg + c * NPIX + j0 + 4 * lj);
        }
        __syncthreads();

        // S = Q^T K  (rows 4ty+r, cols 4tx+cc)
        float s[4][4];
        #pragma unroll
        for (int r = 0; r < 4; r++)
            #pragma unroll
            for (int cc = 0; cc < 4; cc++) s[r][cc] = 0.f;

        #pragma unroll 8
        for (int c = 0; c < CH; c++) {
            float4 q = *(float4*)(Qs + c * 64 + 4 * ty);
            float4 k = *(float4*)(Ks + c * 64 + 4 * tx);
            s[0][0] += q.x * k.x; s[0][1] += q.x * k.y; s[0][2] += q.x * k.z; s[0][3] += q.x * k.w;
            s[1][0] += q.y * k.x; s[1][1] += q.y * k.y; s[1][2] += q.y * k.z; s[1][3] += q.y * k.w;
            s[2][0] += q.z * k.x; s[2][1] += q.z * k.y; s[2][2] += q.z * k.z; s[2][3] += q.z * k.w;
            s[3][0] += q.w * k.x; s[3][1] += q.w * k.y; s[3][2] += q.w * k.z; s[3][3] += q.w * k.w;
        }

        // online softmax (row stats reduced across 16 tx lanes)
        #pragma unroll
        for (int r = 0; r < 4; r++) {
            #pragma unroll
            for (int cc = 0; cc < 4; cc++) s[r][cc] *= SCALE;
            float mx = fmaxf(fmaxf(s[r][0], s[r][1]), fmaxf(s[r][2], s[r][3]));
            mx = fmaxf(mx, __shfl_xor_sync(0xffffffffu, mx, 8));
            mx = fmaxf(mx, __shfl_xor_sync(0xffffffffu, mx, 4));
            mx = fmaxf(mx, __shfl_xor_sync(0xffffffffu, mx, 2));
            mx = fmaxf(mx, __shfl_xor_sync(0xffffffffu, mx, 1));
            const float nm = fmaxf(m[r], mx);
            const float al = __expf(m[r] - nm);
            float ps = 0.f;
            #pragma unroll
            for (int cc = 0; cc < 4; cc++) {
                s[r][cc] = __expf(s[r][cc] - nm);
                ps += s[r][cc];
            }
            ps += __shfl_xor_sync(0xffffffffu, ps, 8);
            ps += __shfl_xor_sync(0xffffffffu, ps, 4);
            ps += __shfl_xor_sync(0xffffffffu, ps, 2);
            ps += __shfl_xor_sync(0xffffffffu, ps, 1);
            l[r] = l[r] * al + ps;
            m[r] = nm;
            #pragma unroll
            for (int i = 0; i < 16; i++) o[r][i] *= al;
        }

        // write P transposed: Pst[col][row], rows contiguous -> float4
        #pragma unroll
        for (int cc = 0; cc < 4; cc++) {
            float4 pv = make_float4(s[0][cc], s[1][cc], s[2][cc], s[3][cc]);
            *(float4*)(Pst + (4 * tx + cc) * 68 + 4 * ty) = pv;
        }
        __syncthreads();

        // O += P * V   (thread owns rows 4ty+r, channels c = tx + 16*i)
        #pragma unroll 2
        for (int j4 = 0; j4 < 16; j4++) {
            float4 p0 = *(float4*)(Pst + (4 * j4 + 0) * 68 + 4 * ty);
            float4 p1 = *(float4*)(Pst + (4 * j4 + 1) * 68 + 4 * ty);
            float4 p2 = *(float4*)(Pst + (4 * j4 + 2) * 68 + 4 * ty);
            float4 p3 = *(float4*)(Pst + (4 * j4 + 3) * 68 + 4 * ty);
            #pragma unroll
            for (int i = 0; i < 16; i++) {
                float4 v = *(float4*)(Vs + (tx + 16 * i) * 68 + 4 * j4);
                o[0][i] += p0.x * v.x + p1.x * v.y + p2.x * v.z + p3.x * v.w;
                o[1][i] += p0.y * v.x + p1.y * v.y + p2.y * v.z + p3.y * v.w;
                o[2][i] += p0.z * v.x + p1.z * v.y + p2.z * v.z + p3.z * v.w;
                o[3][i] += p0.w * v.x + p1.w * v.y + p2.w * v.z + p3.w * v.w;
            }
        }
    }

    // epilogue: g_o[b][c][n] = O[n][c] / l
    float* Og = g_o + b * CH * NPIX;
    #pragma unroll
    for (int r = 0; r < 4; r++) {
        const float inv = 1.f / l[r];
        #pragma unroll
        for (int i = 0; i < 16; i++)
            Og[(tx + 16 * i) * NPIX + n0 + 4 * ty + r] = o[r][i] * inv;
    }
}

// ---------------- launch ----------------
extern "C" void kernel_launch(void* const* d_in, const int* in_sizes, int n_in,
                              void* d_out, int out_size) {
    const float* x      = (const float*)d_in[0];
    const float* gn_w   = (const float*)d_in[1];
    const float* gn_b   = (const float*)d_in[2];
    const float* qkv_w  = (const float*)d_in[3];
    const float* qkv_b  = (const float*)d_in[4];
    const float* proj_w = (const float*)d_in[5];
    const float* proj_b = (const float*)d_in[6];
    float* out = (float*)d_out;

    gn_kernel<<<BATCH * NG, 256>>>(x, gn_w, gn_b);

    {
        dim3 g(NPIX / 64, (3 * CH) / 64, BATCH);
        qkv_gemm<<<g, 256>>>(qkv_w, qkv_b);
    }
    {
        const size_t smem = (size_t)(2 * 256 * 64 + 256 * 68 + 64 * 68) * sizeof(float); // 218112
        cudaFuncSetAttribute(attn_kernel, cudaFuncAttributeMaxDynamicSharedMemorySize, (int)smem);
        dim3 g(NPIX / 64, BATCH);
        attn_kernel<<<g, 256, smem>>>();
    }
    {
        dim3 g(NPIX / 64, CH / 64, BATCH);
        proj_gemm<<<g, 256>>>(proj_w, proj_b, x, out);
    }
}

// round 4
// speedup vs baseline: 2.4397x; 2.4377x over previous
#include <cuda_runtime.h>
#include <cuda_bf16.h>
#include <math.h>
#include <stdint.h>

#define BATCH 4
#define CH    256
#define NPIX  4096
#define CPG   8
#define SCALE 0.0625f

__device__ float g_h  [BATCH * CH * NPIX];
__device__ float g_qkv[BATCH * 3 * CH * NPIX];
__device__ float g_o  [BATCH * CH * NPIX];
__device__ __nv_bfloat16 g_qh[(size_t)BATCH * NPIX * CH];
__device__ __nv_bfloat16 g_ql[(size_t)BATCH * NPIX * CH];
__device__ __nv_bfloat16 g_kh[(size_t)BATCH * NPIX * CH];
__device__ __nv_bfloat16 g_kl[(size_t)BATCH * NPIX * CH];
__device__ __nv_bfloat16 g_vh[(size_t)BATCH * CH * NPIX];
__device__ __nv_bfloat16 g_vl[(size_t)BATCH * CH * NPIX];
__device__ float g_S [(size_t)BATCH * NPIX * NPIX];
__device__ __nv_bfloat16 g_ph[(size_t)BATCH * NPIX * NPIX];
__device__ __nv_bfloat16 g_pl[(size_t)BATCH * NPIX * NPIX];

#define SWZ(o) ((o) ^ (((o) >> 3) & 0x70))

__device__ __forceinline__ uint32_t smem_u32(const void* p) {
    uint32_t a;
    asm("{ .reg .u64 t; cvta.to.shared.u64 t, %1; cvt.u32.u64 %0, t; }" : "=r"(a) : "l"(p));
    return a;
}
__device__ __forceinline__ void cp16(uint32_t dst, const void* src) {
    asm volatile("cp.async.cg.shared.global [%0], [%1], 16;" :: "r"(dst), "l"(src) : "memory");
}
__device__ __forceinline__ void ldm4(uint32_t* r, uint32_t addr) {
    asm volatile("ldmatrix.sync.aligned.m8n8.x4.shared.b16 {%0,%1,%2,%3}, [%4];"
                 : "=r"(r[0]), "=r"(r[1]), "=r"(r[2]), "=r"(r[3]) : "r"(addr));
}
__device__ __forceinline__ void mma16816(float* c, const uint32_t* a, const uint32_t* b) {
    asm volatile("mma.sync.aligned.m16n8k16.row.col.f32.bf16.bf16.f32 "
                 "{%0,%1,%2,%3}, {%4,%5,%6,%7}, {%8,%9}, {%0,%1,%2,%3};"
                 : "+f"(c[0]), "+f"(c[1]), "+f"(c[2]), "+f"(c[3])
                 : "r"(a[0]), "r"(a[1]), "r"(a[2]), "r"(a[3]), "r"(b[0]), "r"(b[1]));
}

// copy one K-chunk: 4 tiles of 128 rows x 64 bf16 (SW128-swizzled, 128B pitch in smem)
__device__ __forceinline__ void cp_chunk(uint32_t stb,
                                         const __nv_bfloat16* Ah, const __nv_bfloat16* Al,
                                         const __nv_bfloat16* Bh, const __nv_bfloat16* Bl,
                                         long pitch, long k0) {
    #pragma unroll
    for (int t = 0; t < 4; t++) {
        const int idx = threadIdx.x + t * 256;
        const int r = idx >> 3, cg = idx & 7;
        const uint32_t doff = SWZ(r * 128 + cg * 16);
        const long soff = (long)r * pitch + k0 + cg * 8;
        cp16(stb + doff,         Ah + soff);
        cp16(stb + 16384 + doff, Al + soff);
        cp16(stb + 32768 + doff, Bh + soff);
        cp16(stb + 49152 + doff, Bl + soff);
    }
}

// one K=64 chunk of 3xBF16 mma for a 32x64 warp tile
__device__ __forceinline__ void mma_chunk(uint32_t sAh, uint32_t sAl, uint32_t sBh, uint32_t sBl,
                                          float (&acc)[2][8][4], int wm, int wn, int lane) {
    const int lr = lane & 15;
    const int lc = (lane >> 4) * 16;
    #pragma unroll
    for (int kk = 0; kk < 4; kk++) {
        const int kb = kk * 32;
        uint32_t ah[2][4], al[2][4];
        #pragma unroll
        for (int mt = 0; mt < 2; mt++) {
            const uint32_t off = SWZ((wm * 32 + mt * 16 + lr) * 128 + kb + lc);
            ldm4(ah[mt], sAh + off);
            ldm4(al[mt], sAl + off);
        }
        #pragma unroll
        for (int np = 0; np < 4; np++) {
            const uint32_t off = SWZ((wn * 64 + np * 16 + lr) * 128 + kb + lc);
            uint32_t bh[4], bl[4];
            ldm4(bh, sBh + off);
            ldm4(bl, sBl + off);
            uint32_t b0h[2] = {bh[0], bh[2]}, b1h[2] = {bh[1], bh[3]};
            uint32_t b0l[2] = {bl[0], bl[2]}, b1l[2] = {bl[1], bl[3]};
            #pragma unroll
            for (int mt = 0; mt < 2; mt++) {
                mma16816(acc[mt][np * 2],     ah[mt], b0h);
                mma16816(acc[mt][np * 2 + 1], ah[mt], b1h);
                mma16816(acc[mt][np * 2],     ah[mt], b0l);
                mma16816(acc[mt][np * 2 + 1], ah[mt], b1l);
                mma16816(acc[mt][np * 2],     al[mt], b0h);
                mma16816(acc[mt][np * 2 + 1], al[mt], b1h);
            }
        }
    }
}

// ---------- GroupNorm ----------
__global__ void __launch_bounds__(256) gn_kernel(const float* __restrict__ x,
                                                 const float* __restrict__ w,
                                                 const float* __restrict__ bias) {
    const int b = blockIdx.x >> 5, g = blockIdx.x & 31;
    const float* xp = x   + (b * CH + g * CPG) * NPIX;
    float*       hp = g_h + (b * CH + g * CPG) * NPIX;
    const int NE = CPG * NPIX;
    float s = 0.f, ss = 0.f;
    const float4* x4 = (const float4*)xp;
    for (int i = threadIdx.x; i < NE / 4; i += 256) {
        float4 v = x4[i];
        s  += v.x + v.y + v.z + v.w;
        ss += v.x * v.x + v.y * v.y + v.z * v.z + v.w * v.w;
    }
    __shared__ float rs[32], rss[32];
    #pragma unroll
    for (int o = 16; o; o >>= 1) {
        s  += __shfl_xor_sync(~0u, s,  o);
        ss += __shfl_xor_sync(~0u, ss, o);
    }
    const int lane = threadIdx.x & 31, wid = threadIdx.x >> 5;
    if (lane == 0) { rs[wid] = s; rss[wid] = ss; }
    __syncthreads();
    if (wid == 0) {
        s  = (lane < 8) ? rs[lane]  : 0.f;
        ss = (lane < 8) ? rss[lane] : 0.f;
        #pragma unroll
        for (int o = 16; o; o >>= 1) {
            s  += __shfl_xor_sync(~0u, s,  o);
            ss += __shfl_xor_sync(~0u, ss, o);
        }
        if (lane == 0) { rs[0] = s; rss[0] = ss; }
    }
    __syncthreads();
    const float mu   = rs[0] / (float)NE;
    const float rstd = rsqrtf(rss[0] / (float)NE - mu * mu + 1e-5f);
    float4* h4 = (float4*)hp;
    for (int i = threadIdx.x; i < NE / 4; i += 256) {
        const int c = g * CPG + (i >> 10);
        const float wc = w[c] * rstd, bc = bias[c] - mu * wc;
        float4 v = x4[i];
        v.x = v.x * wc + bc; v.y = v.y * wc + bc; v.z = v.z * wc + bc; v.w = v.w * wc + bc;
        h4[i] = v;
    }
}

// ---------- fp32 64x64 GEMM ----------
__device__ __forceinline__ void gemm64_body(const float* __restrict__ W,
                                            const float* __restrict__ bias,
                                            const float* __restrict__ In,
                                            float* __restrict__ Out,
                                            const float* __restrict__ resid) {
    __shared__ float Ws[16][68];
    __shared__ float Hs[16][64];
    const int tid = threadIdx.x;
    const int n0 = blockIdx.x * 64, o0 = blockIdx.y * 64;
    const int tx = tid & 15, ty = tid >> 4;
    const int woo = tid >> 2, wk4 = tid & 3;
    const int hkk = tid >> 4, hn4 = tid & 15;
    float acc[4][4] = {};
    for (int k0 = 0; k0 < CH; k0 += 16) {
        float4 wv = *(const float4*)(W  + (o0 + woo) * CH   + k0 + 4 * wk4);
        float4 hv = *(const float4*)(In + (k0 + hkk) * NPIX + n0 + 4 * hn4);
        __syncthreads();
        Ws[4 * wk4 + 0][woo] = wv.x; Ws[4 * wk4 + 1][woo] = wv.y;
        Ws[4 * wk4 + 2][woo] = wv.z; Ws[4 * wk4 + 3][woo] = wv.w;
        *(float4*)(&Hs[hkk][4 * hn4]) = hv;
        __syncthreads();
        #pragma unroll
        for (int kk = 0; kk < 16; kk++) {
            float4 a = *(float4*)(&Ws[kk][4 * ty]);
            float4 h = *(float4*)(&Hs[kk][4 * tx]);
            acc[0][0] += a.x*h.x; acc[0][1] += a.x*h.y; acc[0][2] += a.x*h.z; acc[0][3] += a.x*h.w;
            acc[1][0] += a.y*h.x; acc[1][1] += a.y*h.y; acc[1][2] += a.y*h.z; acc[1][3] += a.y*h.w;
            acc[2][0] += a.z*h.x; acc[2][1] += a.z*h.y; acc[2][2] += a.z*h.z; acc[2][3] += a.z*h.w;
            acc[3][0] += a.w*h.x; acc[3][1] += a.w*h.y; acc[3][2] += a.w*h.z; acc[3][3] += a.w*h.w;
        }
    }
    #pragma unroll
    for (int r = 0; r < 4; r++) {
        const int o = o0 + 4 * ty + r;
        const float bs = bias[o];
        const int idx = o * NPIX + n0 + 4 * tx;
        float4 res;
        res.x = acc[r][0] + bs; res.y = acc[r][1] + bs;
        res.z = acc[r][2] + bs; res.w = acc[r][3] + bs;
        if (resid) {
            float4 xv = *(const float4*)(resid + idx);
            res.x += xv.x; res.y += xv.y; res.z += xv.z; res.w += xv.w;
        }
        *(float4*)(Out + idx) = res;
    }
}
__global__ void __launch_bounds__(256) qkv_gemm(const float* __restrict__ W,
                                                const float* __restrict__ bias) {
    gemm64_body(W, bias, g_h + blockIdx.z * CH * NPIX, g_qkv + blockIdx.z * 3 * CH * NPIX, nullptr);
}
__global__ void __launch_bounds__(256) proj_gemm(const float* __restrict__ W,
                                                 const float* __restrict__ bias,
                                                 const float* __restrict__ x,
                                                 float* __restrict__ out) {
    const int b = blockIdx.z;
    gemm64_body(W, bias, g_o + b * CH * NPIX, out + b * CH * NPIX, x + b * CH * NPIX);
}

// ---------- q/k transpose + hi/lo split ----------
__global__ void __launch_bounds__(256) qk_convert() {
    __shared__ float t[32][33];
    const int n0 = blockIdx.x * 32, c0 = blockIdx.y * 32;
    const int b = blockIdx.z >> 1, sel = blockIdx.z & 1;
    const float* src = g_qkv + ((size_t)b * 3 * CH + sel * CH + c0) * NPIX + n0;
    const int tx = threadIdx.x & 31, ty = threadIdx.x >> 5;
    #pragma unroll
    for (int j = 0; j < 4; j++)
        t[ty + 8 * j][tx] = src[(size_t)(ty + 8 * j) * NPIX + tx];
    __syncthreads();
    __nv_bfloat16* dh = sel ? g_kh : g_qh;
    __nv_bfloat16* dl = sel ? g_kl : g_ql;
    const size_t dbase = ((size_t)b * NPIX + n0) * CH + c0;
    #pragma unroll
    for (int j = 0; j < 4; j++) {
        float v = t[tx][ty + 8 * j];
        __nv_bfloat16 h = __float2bfloat16(v);
        dh[dbase + (size_t)(ty + 8 * j) * CH + tx] = h;
        dl[dbase + (size_t)(ty + 8 * j) * CH + tx] = __float2bfloat16(v - __bfloat162float(h));
    }
}
// ---------- v hi/lo split ----------
__global__ void __launch_bounds__(256) v_convert() {
    const size_t f = (size_t)blockIdx.x * 256 + threadIdx.x;
    const size_t b = f >> 18, rem = f & 262143;
    float4 v = *(const float4*)(g_qkv + ((size_t)b * 3 * CH + 2 * CH) * NPIX + rem * 4);
    const size_t o = (size_t)b * CH * NPIX + rem * 4;
    __nv_bfloat162 h0, h1, l0, l1;
    h0.x = __float2bfloat16(v.x); h0.y = __float2bfloat16(v.y);
    h1.x = __float2bfloat16(v.z); h1.y = __float2bfloat16(v.w);
    l0.x = __float2bfloat16(v.x - __bfloat162float(h0.x));
    l0.y = __float2bfloat16(v.y - __bfloat162float(h0.y));
    l1.x = __float2bfloat16(v.z - __bfloat162float(h1.x));
    l1.y = __float2bfloat16(v.w - __bfloat162float(h1.y));
    *(__nv_bfloat162*)(g_vh + o) = h0; *(__nv_bfloat162*)(g_vh + o + 2) = h1;
    *(__nv_bfloat162*)(g_vl + o) = l0; *(__nv_bfloat162*)(g_vl + o + 2) = l1;
}

// ---------- S = Q K^T (HMMA, CTA 128x128, K=256) ----------
__global__ void __launch_bounds__(256, 1) s_gemm_kernel() {
    extern __shared__ char smem[];
    const uint32_t sb = smem_u32(smem);
    const int tid = threadIdx.x, lane = tid & 31, wid = tid >> 5;
    const int wm = wid & 3, wn = wid >> 2;
    const int b = blockIdx.z, i0 = blockIdx.y * 128, j0 = blockIdx.x * 128;

    const __nv_bfloat16* Ah = g_qh + ((size_t)b * NPIX + i0) * CH;
    const __nv_bfloat16* Al = g_ql + ((size_t)b * NPIX + i0) * CH;
    const __nv_bfloat16* Bh = g_kh + ((size_t)b * NPIX + j0) * CH;
    const __nv_bfloat16* Bl = g_kl + ((size_t)b * NPIX + j0) * CH;

    float acc[2][8][4] = {};

    cp_chunk(sb, Ah, Al, Bh, Bl, CH, 0);
    asm volatile("cp.async.commit_group;" ::: "memory");

    for (int ch = 0; ch < 4; ch++) {
        const uint32_t stb = sb + (ch & 1) * 65536;
        if (ch + 1 < 4) {
            cp_chunk(sb + ((ch + 1) & 1) * 65536, Ah, Al, Bh, Bl, CH, (ch + 1) * 64);
            asm volatile("cp.async.commit_group;" ::: "memory");
            asm volatile("cp.async.wait_group 1;" ::: "memory");
        } else {
            asm volatile("cp.async.wait_group 0;" ::: "memory");
        }
        __syncthreads();
        mma_chunk(stb, stb + 16384, stb + 32768, stb + 49152, acc, wm, wn, lane);
        __syncthreads();
    }

    float* Sb = g_S + ((size_t)b * NPIX + i0) * NPIX + j0;
    const int r0 = wm * 32 + (lane >> 2), c0 = wn * 64 + (lane & 3) * 2;
    #pragma unroll
    for (int mt = 0; mt < 2; mt++)
        #pragma unroll
        for (int nt = 0; nt < 8; nt++) {
            float* p = Sb + (size_t)(r0 + mt * 16) * NPIX + c0 + nt * 8;
            *(float2*)p = make_float2(acc[mt][nt][0], acc[mt][nt][1]);
            *(float2*)(p + (size_t)8 * NPIX) = make_float2(acc[mt][nt][2], acc[mt][nt][3]);
        }
}

// ---------- softmax rows -> P hi/lo ----------
__global__ void __launch_bounds__(256) softmax_kernel() {
    const size_t row = blockIdx.x;
    const float4* s4 = (const float4*)(g_S + row * NPIX);
    const int tid = threadIdx.x, lane = tid & 31, wid = tid >> 5;
    __shared__ float rmax[8], rsum[8];
    float4 v[4];
    float mx = -1e30f;
    #pragma unroll
    for (int k = 0; k < 4; k++) {
        float4 t = s4[tid + 256 * k];
        t.x *= SCALE; t.y *= SCALE; t.z *= SCALE; t.w *= SCALE;
        v[k] = t;
        mx = fmaxf(mx, fmaxf(fmaxf(t.x, t.y), fmaxf(t.z, t.w)));
    }
    #pragma unroll
    for (int o = 16; o; o >>= 1) mx = fmaxf(mx, __shfl_xor_sync(~0u, mx, o));
    if (lane == 0) rmax[wid] = mx;
    __syncthreads();
    mx = rmax[0];
    #pragma unroll
    for (int i = 1; i < 8; i++) mx = fmaxf(mx, rmax[i]);
    float sum = 0.f;
    #pragma unroll
    for (int k = 0; k < 4; k++) {
        v[k].x = __expf(v[k].x - mx); v[k].y = __expf(v[k].y - mx);
        v[k].z = __expf(v[k].z - mx); v[k].w = __expf(v[k].w - mx);
        sum += v[k].x + v[k].y + v[k].z + v[k].w;
    }
    #pragma unroll
    for (int o = 16; o; o >>= 1) sum += __shfl_xor_sync(~0u, sum, o);
    if (lane == 0) rsum[wid] = sum;
    __syncthreads();
    sum = rsum[0]+rsum[1]+rsum[2]+rsum[3]+rsum[4]+rsum[5]+rsum[6]+rsum[7];
    const float inv = 1.f / sum;
    __nv_bfloat16* ph = g_ph + row * NPIX;
    __nv_bfloat16* pl = g_pl + row * NPIX;
    #pragma unroll
    for (int k = 0; k < 4; k++) {
        const int e0 = (tid + 256 * k) * 4;
        float p0 = v[k].x*inv, p1 = v[k].y*inv, p2 = v[k].z*inv, p3 = v[k].w*inv;
        __nv_bfloat162 h0, h1, l0, l1;
        h0.x = __float2bfloat16(p0); h0.y = __float2bfloat16(p1);
        h1.x = __float2bfloat16(p2); h1.y = __float2bfloat16(p3);
        l0.x = __float2bfloat16(p0 - __bfloat162float(h0.x));
        l0.y = __float2bfloat16(p1 - __bfloat162float(h0.y));
        l1.x = __float2bfloat16(p2 - __bfloat162float(h1.x));
        l1.y = __float2bfloat16(p3 - __bfloat162float(h1.y));
        *(__nv_bfloat162*)(ph + e0) = h0; *(__nv_bfloat162*)(ph + e0 + 2) = h1;
        *(__nv_bfloat162*)(pl + e0) = l0; *(__nv_bfloat162*)(pl + e0 + 2) = l1;
    }
}

// ---------- O = P V (HMMA, CTA 128x128, K=4096) ----------
__global__ void __launch_bounds__(256, 1) pv_gemm_kernel() {
    extern __shared__ char smem[];
    const uint32_t sb = smem_u32(smem);
    const int tid = threadIdx.x, lane = tid & 31, wid = tid >> 5;
    const int wm = wid & 3, wn = wid >> 2;
    const int b = blockIdx.z, i0 = blockIdx.x * 128, cHalf = blockIdx.y;

    const __nv_bfloat16* Ah = g_ph + ((size_t)b * NPIX + i0) * NPIX;
    const __nv_bfloat16* Al = g_pl + ((size_t)b * NPIX + i0) * NPIX;
    const __nv_bfloat16* Bh = g_vh + ((size_t)b * CH + cHalf * 128) * NPIX;
    const __nv_bfloat16* Bl = g_vl + ((size_t)b * CH + cHalf * 128) * NPIX;

    float acc[2][8][4] = {};

    cp_chunk(sb, Ah, Al, Bh, Bl, NPIX, 0);
    asm volatile("cp.async.commit_group;" ::: "memory");

    for (int ch = 0; ch < 64; ch++) {
        const uint32_t stb = sb + (ch & 1) * 65536;
        if (ch + 1 < 64) {
            cp_chunk(sb + ((ch + 1) & 1) * 65536, Ah, Al, Bh, Bl, NPIX, (long)(ch + 1) * 64);
            asm volatile("cp.async.commit_group;" ::: "memory");
            asm volatile("cp.async.wait_group 1;" ::: "memory");
        } else {
            asm volatile("cp.async.wait_group 0;" ::: "memory");
        }
        __syncthreads();
        mma_chunk(stb, stb + 16384, stb + 32768, stb + 49152, acc, wm, wn, lane);
        __syncthreads();
    }

    // epilogue: O[i][c] -> g_o[b][c][i]
    float* Ob = g_o + (size_t)b * CH * NPIX;
    const int rb = i0 + wm * 32 + (lane >> 2);
    const int cb = cHalf * 128 + wn * 64 + (lane & 3) * 2;
    #pragma unroll
    for (int mt = 0; mt < 2; mt++)
        #pragma unroll
        for (int nt = 0; nt < 8; nt++) {
            const int r = rb + mt * 16;
            const int c = cb + nt * 8;
            Ob[(size_t)c * NPIX + r]           = acc[mt][nt][0];
            Ob[(size_t)(c + 1) * NPIX + r]     = acc[mt][nt][1];
            Ob[(size_t)c * NPIX + r + 8]       = acc[mt][nt][2];
            Ob[(size_t)(c + 1) * NPIX + r + 8] = acc[mt][nt][3];
        }
}

// ---------- launch ----------
extern "C" void kernel_launch(void* const* d_in, const int* in_sizes, int n_in,
                              void* d_out, int out_size) {
    const float* x      = (const float*)d_in[0];
    const float* gn_w   = (const float*)d_in[1];
    const float* gn_b   = (const float*)d_in[2];
    const float* qkv_w  = (const float*)d_in[3];
    const float* qkv_b  = (const float*)d_in[4];
    const float* proj_w = (const float*)d_in[5];
    const float* proj_b = (const float*)d_in[6];
    float* out = (float*)d_out;

    gn_kernel<<<BATCH * 32, 256>>>(x, gn_w, gn_b);
    {
        dim3 g(NPIX / 64, (3 * CH) / 64, BATCH);
        qkv_gemm<<<g, 256>>>(qkv_w, qkv_b);
    }
    {
        dim3 g(NPIX / 32, CH / 32, BATCH * 2);
        qk_convert<<<g, 256>>>();
    }
    v_convert<<<(BATCH * CH * NPIX) / (256 * 4), 256>>>();
    {
        const int smem = 131072;
        cudaFuncSetAttribute(s_gemm_kernel, cudaFuncAttributeMaxDynamicSharedMemorySize, smem);
        dim3 g(NPIX / 128, NPIX / 128, BATCH);
        s_gemm_kernel<<<g, 256, smem>>>();
    }
    softmax_kernel<<<BATCH * NPIX, 256>>>();
    {
        const int smem = 131072;
        cudaFuncSetAttribute(pv_gemm_kernel, cudaFuncAttributeMaxDynamicSharedMemorySize, smem);
        dim3 g(NPIX / 128, 2, BATCH);
        pv_gemm_kernel<<<g, 256, smem>>>();
    }
    {
        dim3 g(NPIX / 64, CH / 64, BATCH);
        proj_gemm<<<g, 256>>>(proj_w, proj_b, x, out);
    }
}

// round 5
// speedup vs baseline: 2.8682x; 1.1756x over previous
#include <cuda_runtime.h>
#include <cuda_bf16.h>
#include <math.h>
#include <stdint.h>

#define BATCH 4
#define CH    256
#define NPIX  4096
#define CPG   8
#define SCALE 0.0625f

__device__ float g_h [BATCH * CH * NPIX];
__device__ __nv_bfloat16 g_hh[(size_t)BATCH * NPIX * CH];
__device__ __nv_bfloat16 g_hl[(size_t)BATCH * NPIX * CH];
__device__ __nv_bfloat16 g_wqh[3 * CH * CH], g_wql[3 * CH * CH];
__device__ __nv_bfloat16 g_wph[CH * CH],     g_wpl[CH * CH];
__device__ __nv_bfloat16 g_qh[(size_t)BATCH * NPIX * CH];
__device__ __nv_bfloat16 g_ql[(size_t)BATCH * NPIX * CH];
__device__ __nv_bfloat16 g_kh[(size_t)BATCH * NPIX * CH];
__device__ __nv_bfloat16 g_kl[(size_t)BATCH * NPIX * CH];
__device__ __nv_bfloat16 g_vh[(size_t)BATCH * CH * NPIX];
__device__ __nv_bfloat16 g_vl[(size_t)BATCH * CH * NPIX];
__device__ float g_S [(size_t)BATCH * NPIX * NPIX];
__device__ __nv_bfloat16 g_ph[(size_t)BATCH * NPIX * NPIX];
__device__ __nv_bfloat16 g_pl[(size_t)BATCH * NPIX * NPIX];
__device__ __nv_bfloat16 g_oh[(size_t)BATCH * NPIX * CH];
__device__ __nv_bfloat16 g_ol[(size_t)BATCH * NPIX * CH];

#define SWZ(o) ((o) ^ (((o) >> 3) & 0x70))

__device__ __forceinline__ uint32_t smem_u32(const void* p) {
    uint32_t a;
    asm("{ .reg .u64 t; cvta.to.shared.u64 t, %1; cvt.u32.u64 %0, t; }" : "=r"(a) : "l"(p));
    return a;
}
__device__ __forceinline__ void cp16(uint32_t dst, const void* src) {
    asm volatile("cp.async.cg.shared.global [%0], [%1], 16;" :: "r"(dst), "l"(src) : "memory");
}
__device__ __forceinline__ void ldm4(uint32_t* r, uint32_t addr) {
    asm volatile("ldmatrix.sync.aligned.m8n8.x4.shared.b16 {%0,%1,%2,%3}, [%4];"
                 : "=r"(r[0]), "=r"(r[1]), "=r"(r[2]), "=r"(r[3]) : "r"(addr));
}
__device__ __forceinline__ void mma16816(float* c, const uint32_t* a, const uint32_t* b) {
    asm volatile("mma.sync.aligned.m16n8k16.row.col.f32.bf16.bf16.f32 "
                 "{%0,%1,%2,%3}, {%4,%5,%6,%7}, {%8,%9}, {%0,%1,%2,%3};"
                 : "+f"(c[0]), "+f"(c[1]), "+f"(c[2]), "+f"(c[3])
                 : "r"(a[0]), "r"(a[1]), "r"(a[2]), "r"(a[3]), "r"(b[0]), "r"(b[1]));
}
__device__ __forceinline__ void split2(float a, float b, __nv_bfloat162* h, __nv_bfloat162* l) {
    h->x = __float2bfloat16(a); h->y = __float2bfloat16(b);
    l->x = __float2bfloat16(a - __bfloat162float(h->x));
    l->y = __float2bfloat16(b - __bfloat162float(h->y));
}

__device__ __forceinline__ void cp_chunk(uint32_t stb,
                                         const __nv_bfloat16* Ah, const __nv_bfloat16* Al,
                                         const __nv_bfloat16* Bh, const __nv_bfloat16* Bl,
                                         long pitch, long k0) {
    #pragma unroll
    for (int t = 0; t < 4; t++) {
        const int idx = threadIdx.x + t * 256;
        const int r = idx >> 3, cg = idx & 7;
        const uint32_t doff = SWZ(r * 128 + cg * 16);
        const long soff = (long)r * pitch + k0 + cg * 8;
        cp16(stb + doff,         Ah + soff);
        cp16(stb + 16384 + doff, Al + soff);
        cp16(stb + 32768 + doff, Bh + soff);
        cp16(stb + 49152 + doff, Bl + soff);
    }
}

__device__ __forceinline__ void mma_chunk(uint32_t sAh, uint32_t sAl, uint32_t sBh, uint32_t sBl,
                                          float (&acc)[2][8][4], int wm, int wn, int lane) {
    const int lr = lane & 15;
    const int lc = (lane >> 4) * 16;
    #pragma unroll
    for (int kk = 0; kk < 4; kk++) {
        const int kb = kk * 32;
        uint32_t ah[2][4], al[2][4];
        #pragma unroll
        for (int mt = 0; mt < 2; mt++) {
            const uint32_t off = SWZ((wm * 32 + mt * 16 + lr) * 128 + kb + lc);
            ldm4(ah[mt], sAh + off);
            ldm4(al[mt], sAl + off);
        }
        #pragma unroll
        for (int np = 0; np < 4; np++) {
            const uint32_t off = SWZ((wn * 64 + np * 16 + lr) * 128 + kb + lc);
            uint32_t bh[4], bl[4];
            ldm4(bh, sBh + off);
            ldm4(bl, sBl + off);
            uint32_t b0h[2] = {bh[0], bh[2]}, b1h[2] = {bh[1], bh[3]};
            uint32_t b0l[2] = {bl[0], bl[2]}, b1l[2] = {bl[1], bl[3]};
            #pragma unroll
            for (int mt = 0; mt < 2; mt++) {
                mma16816(acc[mt][np * 2],     ah[mt], b0h);
                mma16816(acc[mt][np * 2 + 1], ah[mt], b1h);
                mma16816(acc[mt][np * 2],     ah[mt], b0l);
                mma16816(acc[mt][np * 2 + 1], ah[mt], b1l);
                mma16816(acc[mt][np * 2],     al[mt], b0h);
                mma16816(acc[mt][np * 2 + 1], al[mt], b1h);
            }
        }
    }
}

__device__ __forceinline__ void hmma_pipeline(uint32_t sb,
        const __nv_bfloat16* Ah, const __nv_bfloat16* Al,
        const __nv_bfloat16* Bh, const __nv_bfloat16* Bl,
        long pitch, int nch, float (&acc)[2][8][4], int wm, int wn, int lane) {
    cp_chunk(sb, Ah, Al, Bh, Bl, pitch, 0);
    asm volatile("cp.async.commit_group;" ::: "memory");
    for (int ch = 0; ch < nch; ch++) {
        const uint32_t stb = sb + (ch & 1) * 65536;
        if (ch + 1 < nch) {
            cp_chunk(sb + ((ch + 1) & 1) * 65536, Ah, Al, Bh, Bl, pitch, (long)(ch + 1) * 64);
            asm volatile("cp.async.commit_group;" ::: "memory");
            asm volatile("cp.async.wait_group 1;" ::: "memory");
        } else {
            asm volatile("cp.async.wait_group 0;" ::: "memory");
        }
        __syncthreads();
        mma_chunk(stb, stb + 16384, stb + 32768, stb + 49152, acc, wm, wn, lane);
        __syncthreads();
    }
}

// ---------- GroupNorm ----------
__global__ void __launch_bounds__(256) gn_kernel(const float* __restrict__ x,
                                                 const float* __restrict__ w,
                                                 const float* __restrict__ bias) {
    const int b = blockIdx.x >> 5, g = blockIdx.x & 31;
    const float* xp = x   + (b * CH + g * CPG) * NPIX;
    float*       hp = g_h + (b * CH + g * CPG) * NPIX;
    const int NE = CPG * NPIX;
    float s = 0.f, ss = 0.f;
    const float4* x4 = (const float4*)xp;
    for (int i = threadIdx.x; i < NE / 4; i += 256) {
        float4 v = x4[i];
        s  += v.x + v.y + v.z + v.w;
        ss += v.x * v.x + v.y * v.y + v.z * v.z + v.w * v.w;
    }
    __shared__ float rs[32], rss[32];
    #pragma unroll
    for (int o = 16; o; o >>= 1) {
        s  += __shfl_xor_sync(~0u, s,  o);
        ss += __shfl_xor_sync(~0u, ss, o);
    }
    const int lane = threadIdx.x & 31, wid = threadIdx.x >> 5;
    if (lane == 0) { rs[wid] = s; rss[wid] = ss; }
    __syncthreads();
    if (wid == 0) {
        s  = (lane < 8) ? rs[lane]  : 0.f;
        ss = (lane < 8) ? rss[lane] : 0.f;
        #pragma unroll
        for (int o = 16; o; o >>= 1) {
            s  += __shfl_xor_sync(~0u, s,  o);
            ss += __shfl_xor_sync(~0u, ss, o);
        }
        if (lane == 0) { rs[0] = s; rss[0] = ss; }
    }
    __syncthreads();
    const float mu   = rs[0] / (float)NE;
    const float rstd = rsqrtf(rss[0] / (float)NE - mu * mu + 1e-5f);
    float4* h4 = (float4*)hp;
    for (int i = threadIdx.x; i < NE / 4; i += 256) {
        const int c = g * CPG + (i >> 10);
        const float wc = w[c] * rstd, bc = bias[c] - mu * wc;
        float4 v = x4[i];
        v.x = v.x * wc + bc; v.y = v.y * wc + bc; v.z = v.z * wc + bc; v.w = v.w * wc + bc;
        h4[i] = v;
    }
}

// ---------- h: [c][n] fp32 -> [n][c] hi/lo bf16 ----------
__global__ void __launch_bounds__(256) h_convert() {
    __shared__ float t[32][33];
    const int n0 = blockIdx.x * 32, c0 = blockIdx.y * 32, b = blockIdx.z;
    const float* src = g_h + ((size_t)b * CH + c0) * NPIX + n0;
    const int tx = threadIdx.x & 31, ty = threadIdx.x >> 5;
    #pragma unroll
    for (int j = 0; j < 4; j++)
        t[ty + 8 * j][tx] = src[(size_t)(ty + 8 * j) * NPIX + tx];
    __syncthreads();
    const size_t dbase = ((size_t)b * NPIX + n0) * CH + c0;
    #pragma unroll
    for (int j = 0; j < 4; j++) {
        float v = t[tx][ty + 8 * j];
        __nv_bfloat16 h = __float2bfloat16(v);
        g_hh[dbase + (size_t)(ty + 8 * j) * CH + tx] = h;
        g_hl[dbase + (size_t)(ty + 8 * j) * CH + tx] = __float2bfloat16(v - __bfloat162float(h));
    }
}

// ---------- weight split ----------
__global__ void __launch_bounds__(256) w_convert(const float* __restrict__ qkv_w,
                                                 const float* __restrict__ proj_w) {
    const int f4 = blockIdx.x * 256 + threadIdx.x;   // 65536 float4s total
    const float* src;
    __nv_bfloat16 *dh, *dl;
    size_t e;
    if (f4 < 49152) { src = qkv_w;  dh = g_wqh; dl = g_wql; e = (size_t)f4 * 4; }
    else            { src = proj_w; dh = g_wph; dl = g_wpl; e = (size_t)(f4 - 49152) * 4; }
    float4 v = *(const float4*)(src + e);
    __nv_bfloat162 h0, h1, l0, l1;
    split2(v.x, v.y, &h0, &l0);
    split2(v.z, v.w, &h1, &l1);
    *(__nv_bfloat162*)(dh + e)     = h0; *(__nv_bfloat162*)(dh + e + 2) = h1;
    *(__nv_bfloat162*)(dl + e)     = l0; *(__nv_bfloat162*)(dl + e + 2) = l1;
}

// ---------- QKV = W_qkv * H  (HMMA; epilogue emits q,k [n][c] and v [c][n] hi/lo) ----------
__global__ void __launch_bounds__(256, 1) qkv_hmma(const float* __restrict__ qkv_b) {
    extern __shared__ char smem[];
    const uint32_t sb = smem_u32(smem);
    const int tid = threadIdx.x, lane = tid & 31, wid = tid >> 5;
    const int wm = wid & 3, wn = wid >> 2;
    const int b = blockIdx.z, n0 = blockIdx.x * 128, o0 = blockIdx.y * 128;

    const __nv_bfloat16* Ah = g_wqh + (size_t)o0 * CH;
    const __nv_bfloat16* Al = g_wql + (size_t)o0 * CH;
    const __nv_bfloat16* Bh = g_hh + ((size_t)b * NPIX + n0) * CH;
    const __nv_bfloat16* Bl = g_hl + ((size_t)b * NPIX + n0) * CH;

    float acc[2][8][4] = {};
    hmma_pipeline(sb, Ah, Al, Bh, Bl, CH, 4, acc, wm, wn, lane);

    const int r0 = wm * 32 + (lane >> 2), c0 = wn * 64 + (lane & 3) * 2;
    #pragma unroll
    for (int mt = 0; mt < 2; mt++) {
        const float b0 = qkv_b[o0 + r0 + mt * 16];
        const float b1 = qkv_b[o0 + r0 + mt * 16 + 8];
        #pragma unroll
        for (int nt = 0; nt < 8; nt++) {
            acc[mt][nt][0] += b0; acc[mt][nt][1] += b0;
            acc[mt][nt][2] += b1; acc[mt][nt][3] += b1;
        }
    }

    const int sel = blockIdx.y >> 1;   // 0=q, 1=k, 2=v
    if (sel == 2) {
        // v: [c][n] direct
        __nv_bfloat16* vh = g_vh + ((size_t)b * CH + (o0 - 512)) * NPIX + n0;
        __nv_bfloat16* vl = g_vl + ((size_t)b * CH + (o0 - 512)) * NPIX + n0;
        #pragma unroll
        for (int mt = 0; mt < 2; mt++)
            #pragma unroll
            for (int nt = 0; nt < 8; nt++) {
                const int rr = r0 + mt * 16, cc = c0 + nt * 8;
                __nv_bfloat162 h, l;
                split2(acc[mt][nt][0], acc[mt][nt][1], &h, &l);
                *(__nv_bfloat162*)(vh + (size_t)rr * NPIX + cc) = h;
                *(__nv_bfloat162*)(vl + (size_t)rr * NPIX + cc) = l;
                split2(acc[mt][nt][2], acc[mt][nt][3], &h, &l);
                *(__nv_bfloat162*)(vh + (size_t)(rr + 8) * NPIX + cc) = h;
                *(__nv_bfloat162*)(vl + (size_t)(rr + 8) * NPIX + cc) = l;
            }
    } else {
        // q/k: transpose via smem -> [n][c]
        float* st = (float*)smem;   // [n 128][o 132]
        #pragma unroll
        for (int mt = 0; mt < 2; mt++)
            #pragma unroll
            for (int nt = 0; nt < 8; nt++) {
                const int rr = r0 + mt * 16, cc = c0 + nt * 8;
                st[(cc)     * 132 + rr]     = acc[mt][nt][0];
                st[(cc + 1) * 132 + rr]     = acc[mt][nt][1];
                st[(cc)     * 132 + rr + 8] = acc[mt][nt][2];
                st[(cc + 1) * 132 + rr + 8] = acc[mt][nt][3];
            }
        __syncthreads();
        __nv_bfloat16* dh = (sel ? g_kh : g_qh) + ((size_t)b * NPIX + n0) * CH + (o0 - sel * 256);
        __nv_bfloat16* dl = (sel ? g_kl : g_ql) + ((size_t)b * NPIX + n0) * CH + (o0 - sel * 256);
        const int o4 = lane * 4, nb = tid >> 5;
        #pragma unroll
        for (int j = 0; j < 16; j++) {
            const int n = nb + 8 * j;
            float4 v = *(float4*)(st + n * 132 + o4);
            __nv_bfloat162 h0, h1, l0, l1;
            split2(v.x, v.y, &h0, &l0);
            split2(v.z, v.w, &h1, &l1);
            *(__nv_bfloat162*)(dh + (size_t)n * CH + o4)     = h0;
            *(__nv_bfloat162*)(dh + (size_t)n * CH + o4 + 2) = h1;
            *(__nv_bfloat162*)(dl + (size_t)n * CH + o4)     = l0;
            *(__nv_bfloat162*)(dl + (size_t)n * CH + o4 + 2) = l1;
        }
    }
}

// ---------- S = Q K^T (HMMA, CTA 128x128, K=256) ----------
__global__ void __launch_bounds__(256, 1) s_gemm_kernel() {
    extern __shared__ char smem[];
    const uint32_t sb = smem_u32(smem);
    const int tid = threadIdx.x, lane = tid & 31, wid = tid >> 5;
    const int wm = wid & 3, wn = wid >> 2;
    const int b = blockIdx.z, i0 = blockIdx.y * 128, j0 = blockIdx.x * 128;

    const __nv_bfloat16* Ah = g_qh + ((size_t)b * NPIX + i0) * CH;
    const __nv_bfloat16* Al = g_ql + ((size_t)b * NPIX + i0) * CH;
    const __nv_bfloat16* Bh = g_kh + ((size_t)b * NPIX + j0) * CH;
    const __nv_bfloat16* Bl = g_kl + ((size_t)b * NPIX + j0) * CH;

    float acc[2][8][4] = {};
    hmma_pipeline(sb, Ah, Al, Bh, Bl, CH, 4, acc, wm, wn, lane);

    float* Sb = g_S + ((size_t)b * NPIX + i0) * NPIX + j0;
    const int r0 = wm * 32 + (lane >> 2), c0 = wn * 64 + (lane & 3) * 2;
    #pragma unroll
    for (int mt = 0; mt < 2; mt++)
        #pragma unroll
        for (int nt = 0; nt < 8; nt++) {
            float* p = Sb + (size_t)(r0 + mt * 16) * NPIX + c0 + nt * 8;
            *(float2*)p = make_float2(acc[mt][nt][0], acc[mt][nt][1]);
            *(float2*)(p + (size_t)8 * NPIX) = make_float2(acc[mt][nt][2], acc[mt][nt][3]);
        }
}

// ---------- softmax rows -> P hi/lo ----------
__global__ void __launch_bounds__(256) softmax_kernel() {
    const size_t row = blockIdx.x;
    const float4* s4 = (const float4*)(g_S + row * NPIX);
    const int tid = threadIdx.x, lane = tid & 31, wid = tid >> 5;
    __shared__ float rmax[8], rsum[8];
    float4 v[4];
    float mx = -1e30f;
    #pragma unroll
    for (int k = 0; k < 4; k++) {
        float4 t = s4[tid + 256 * k];
        t.x *= SCALE; t.y *= SCALE; t.z *= SCALE; t.w *= SCALE;
        v[k] = t;
        mx = fmaxf(mx, fmaxf(fmaxf(t.x, t.y), fmaxf(t.z, t.w)));
    }
    #pragma unroll
    for (int o = 16; o; o >>= 1) mx = fmaxf(mx, __shfl_xor_sync(~0u, mx, o));
    if (lane == 0) rmax[wid] = mx;
    __syncthreads();
    mx = rmax[0];
    #pragma unroll
    for (int i = 1; i < 8; i++) mx = fmaxf(mx, rmax[i]);
    float sum = 0.f;
    #pragma unroll
    for (int k = 0; k < 4; k++) {
        v[k].x = __expf(v[k].x - mx); v[k].y = __expf(v[k].y - mx);
        v[k].z = __expf(v[k].z - mx); v[k].w = __expf(v[k].w - mx);
        sum += v[k].x + v[k].y + v[k].z + v[k].w;
    }
    #pragma unroll
    for (int o = 16; o; o >>= 1) sum += __shfl_xor_sync(~0u, sum, o);
    if (lane == 0) rsum[wid] = sum;
    __syncthreads();
    sum = rsum[0]+rsum[1]+rsum[2]+rsum[3]+rsum[4]+rsum[5]+rsum[6]+rsum[7];
    const float inv = 1.f / sum;
    __nv_bfloat16* ph = g_ph + row * NPIX;
    __nv_bfloat16* pl = g_pl + row * NPIX;
    #pragma unroll
    for (int k = 0; k < 4; k++) {
        const int e0 = (tid + 256 * k) * 4;
        __nv_bfloat162 h0, h1, l0, l1;
        split2(v[k].x * inv, v[k].y * inv, &h0, &l0);
        split2(v[k].z * inv, v[k].w * inv, &h1, &l1);
        *(__nv_bfloat162*)(ph + e0) = h0; *(__nv_bfloat162*)(ph + e0 + 2) = h1;
        *(__nv_bfloat162*)(pl + e0) = l0; *(__nv_bfloat162*)(pl + e0 + 2) = l1;
    }
}

// ---------- O = P V (HMMA, K=4096; epilogue emits O [n][c] hi/lo) ----------
__global__ void __launch_bounds__(256, 1) pv_gemm_kernel() {
    extern __shared__ char smem[];
    const uint32_t sb = smem_u32(smem);
    const int tid = threadIdx.x, lane = tid & 31, wid = tid >> 5;
    const int wm = wid & 3, wn = wid >> 2;
    const int b = blockIdx.z, i0 = blockIdx.x * 128, cHalf = blockIdx.y;

    const __nv_bfloat16* Ah = g_ph + ((size_t)b * NPIX + i0) * NPIX;
    const __nv_bfloat16* Al = g_pl + ((size_t)b * NPIX + i0) * NPIX;
    const __nv_bfloat16* Bh = g_vh + ((size_t)b * CH + cHalf * 128) * NPIX;
    const __nv_bfloat16* Bl = g_vl + ((size_t)b * CH + cHalf * 128) * NPIX;

    float acc[2][8][4] = {};
    hmma_pipeline(sb, Ah, Al, Bh, Bl, NPIX, 64, acc, wm, wn, lane);

    // acc rows = pixel i, cols = channel c -> exactly O^T [n][c] layout
    __nv_bfloat16* oh = g_oh + ((size_t)b * NPIX + i0) * CH + cHalf * 128;
    __nv_bfloat16* ol = g_ol + ((size_t)b * NPIX + i0) * CH + cHalf * 128;
    const int r0 = wm * 32 + (lane >> 2), c0 = wn * 64 + (lane & 3) * 2;
    #pragma unroll
    for (int mt = 0; mt < 2; mt++)
        #pragma unroll
        for (int nt = 0; nt < 8; nt++) {
            const int rr = r0 + mt * 16, cc = c0 + nt * 8;
            __nv_bfloat162 h, l;
            split2(acc[mt][nt][0], acc[mt][nt][1], &h, &l);
            *(__nv_bfloat162*)(oh + (size_t)rr * CH + cc) = h;
            *(__nv_bfloat162*)(ol + (size_t)rr * CH + cc) = l;
            split2(acc[mt][nt][2], acc[mt][nt][3], &h, &l);
            *(__nv_bfloat162*)(oh + (size_t)(rr + 8) * CH + cc) = h;
            *(__nv_bfloat162*)(ol + (size_t)(rr + 8) * CH + cc) = l;
        }
}

// ---------- out = proj_w * O + proj_b + x  (HMMA) ----------
__global__ void __launch_bounds__(256, 1) proj_hmma(const float* __restrict__ proj_b,
                                                    const float* __restrict__ x,
                                                    float* __restrict__ out) {
    extern __shared__ char smem[];
    const uint32_t sb = smem_u32(smem);
    const int tid = threadIdx.x, lane = tid & 31, wid = tid >> 5;
    const int wm = wid & 3, wn = wid >> 2;
    const int b = blockIdx.z, n0 = blockIdx.x * 128, o0 = blockIdx.y * 128;

    const __nv_bfloat16* Ah = g_wph + (size_t)o0 * CH;
    const __nv_bfloat16* Al = g_wpl + (size_t)o0 * CH;
    const __nv_bfloat16* Bh = g_oh + ((size_t)b * NPIX + n0) * CH;
    const __nv_bfloat16* Bl = g_ol + ((size_t)b * NPIX + n0) * CH;

    float acc[2][8][4] = {};
    hmma_pipeline(sb, Ah, Al, Bh, Bl, CH, 4, acc, wm, wn, lane);

    const int r0 = wm * 32 + (lane >> 2), c0 = wn * 64 + (lane & 3) * 2;
    #pragma unroll
    for (int mt = 0; mt < 2; mt++) {
        const int r  = o0 + r0 + mt * 16;
        const float b0 = proj_b[r], b1 = proj_b[r + 8];
        #pragma unroll
        for (int nt = 0; nt < 8; nt++) {
            const size_t idx0 = ((size_t)b * CH + r) * NPIX + n0 + c0 + nt * 8;
            const size_t idx1 = idx0 + (size_t)8 * NPIX;
            float2 x0 = *(const float2*)(x + idx0);
            float2 x1 = *(const float2*)(x + idx1);
            *(float2*)(out + idx0) = make_float2(acc[mt][nt][0] + b0 + x0.x,
                                                 acc[mt][nt][1] + b0 + x0.y);
            *(float2*)(out + idx1) = make_float2(acc[mt][nt][2] + b1 + x1.x,
                                                 acc[mt][nt][3] + b1 + x1.y);
        }
    }
}

// ---------- launch ----------
extern "C" void kernel_launch(void* const* d_in, const int* in_sizes, int n_in,
                              void* d_out, int out_size) {
    const float* x      = (const float*)d_in[0];
    const float* gn_w   = (const float*)d_in[1];
    const float* gn_b   = (const float*)d_in[2];
    const float* qkv_w  = (const float*)d_in[3];
    const float* qkv_b  = (const float*)d_in[4];
    const float* proj_w = (const float*)d_in[5];
    const float* proj_b = (const float*)d_in[6];
    float* out = (float*)d_out;

    const int SMEM = 131072;
    cudaFuncSetAttribute(qkv_hmma,     cudaFuncAttributeMaxDynamicSharedMemorySize, SMEM);
    cudaFuncSetAttribute(s_gemm_kernel, cudaFuncAttributeMaxDynamicSharedMemorySize, SMEM);
    cudaFuncSetAttribute(pv_gemm_kernel, cudaFuncAttributeMaxDynamicSharedMemorySize, SMEM);
    cudaFuncSetAttribute(proj_hmma,    cudaFuncAttributeMaxDynamicSharedMemorySize, SMEM);

    w_convert<<<256, 256>>>(qkv_w, proj_w);
    gn_kernel<<<BATCH * 32, 256>>>(x, gn_w, gn_b);
    {
        dim3 g(NPIX / 32, CH / 32, BATCH);
        h_convert<<<g, 256>>>();
    }
    {
        dim3 g(NPIX / 128, 6, BATCH);
        qkv_hmma<<<g, 256, SMEM>>>(qkv_b);
    }
    {
        dim3 g(NPIX / 128, NPIX / 128, BATCH);
        s_gemm_kernel<<<g, 256, SMEM>>>();
    }
    softmax_kernel<<<BATCH * NPIX, 256>>>();
    {
        dim3 g(NPIX / 128, 2, BATCH);
        pv_gemm_kernel<<<g, 256, SMEM>>>();
    }
    {
        dim3 g(NPIX / 128, 2, BATCH);
        proj_hmma<<<g, 256, SMEM>>>(proj_b, x, out);
    }
}

// round 6
// speedup vs baseline: 3.2693x; 1.1398x over previous
#include <cuda_runtime.h>
#include <cuda_bf16.h>
#include <cuda_fp16.h>
#include <math.h>
#include <stdint.h>

#define BATCH 4
#define CH    256
#define NPIX  4096
#define CPG   8
#define SCALE 0.0625f

__device__ float g_h [BATCH * CH * NPIX];
__device__ __nv_bfloat16 g_hh[(size_t)BATCH * NPIX * CH];
__device__ __nv_bfloat16 g_hl[(size_t)BATCH * NPIX * CH];
__device__ __nv_bfloat16 g_wqh[3 * CH * CH], g_wql[3 * CH * CH];
__device__ __nv_bfloat16 g_wph[CH * CH],     g_wpl[CH * CH];
__device__ __nv_bfloat16 g_qh[(size_t)BATCH * NPIX * CH];
__device__ __nv_bfloat16 g_ql[(size_t)BATCH * NPIX * CH];
__device__ __nv_bfloat16 g_kh[(size_t)BATCH * NPIX * CH];
__device__ __nv_bfloat16 g_kl[(size_t)BATCH * NPIX * CH];
__device__ __half g_v16h[(size_t)BATCH * CH * NPIX];
__device__ __half g_v16l[(size_t)BATCH * CH * NPIX];
__device__ float g_S [(size_t)BATCH * NPIX * NPIX];
__device__ __half g_p [(size_t)BATCH * NPIX * NPIX];
__device__ __nv_bfloat16 g_oh[(size_t)BATCH * NPIX * CH];
__device__ __nv_bfloat16 g_ol[(size_t)BATCH * NPIX * CH];

#define SWZ(o) ((o) ^ (((o) >> 3) & 0x70))

__device__ __forceinline__ uint32_t smem_u32(const void* p) {
    uint32_t a;
    asm("{ .reg .u64 t; cvta.to.shared.u64 t, %1; cvt.u32.u64 %0, t; }" : "=r"(a) : "l"(p));
    return a;
}
__device__ __forceinline__ void cp16(uint32_t dst, const void* src) {
    asm volatile("cp.async.cg.shared.global [%0], [%1], 16;" :: "r"(dst), "l"(src) : "memory");
}
__device__ __forceinline__ void ldm4(uint32_t* r, uint32_t addr) {
    asm volatile("ldmatrix.sync.aligned.m8n8.x4.shared.b16 {%0,%1,%2,%3}, [%4];"
                 : "=r"(r[0]), "=r"(r[1]), "=r"(r[2]), "=r"(r[3]) : "r"(addr));
}
__device__ __forceinline__ void mma16816(float* c, const uint32_t* a, const uint32_t* b) {
    asm volatile("mma.sync.aligned.m16n8k16.row.col.f32.bf16.bf16.f32 "
                 "{%0,%1,%2,%3}, {%4,%5,%6,%7}, {%8,%9}, {%0,%1,%2,%3};"
                 : "+f"(c[0]), "+f"(c[1]), "+f"(c[2]), "+f"(c[3])
                 : "r"(a[0]), "r"(a[1]), "r"(a[2]), "r"(a[3]), "r"(b[0]), "r"(b[1]));
}
__device__ __forceinline__ void mma16816h(float* c, const uint32_t* a, const uint32_t* b) {
    asm volatile("mma.sync.aligned.m16n8k16.row.col.f32.f16.f16.f32 "
                 "{%0,%1,%2,%3}, {%4,%5,%6,%7}, {%8,%9}, {%0,%1,%2,%3};"
                 : "+f"(c[0]), "+f"(c[1]), "+f"(c[2]), "+f"(c[3])
                 : "r"(a[0]), "r"(a[1]), "r"(a[2]), "r"(a[3]), "r"(b[0]), "r"(b[1]));
}
__device__ __forceinline__ void split2(float a, float b, __nv_bfloat162* h, __nv_bfloat162* l) {
    h->x = __float2bfloat16(a); h->y = __float2bfloat16(b);
    l->x = __float2bfloat16(a - __bfloat162float(h->x));
    l->y = __float2bfloat16(b - __bfloat162float(h->y));
}
__device__ __forceinline__ void split2h(float a, float b, __half2* h, __half2* l) {
    __half ha = __float2half_rn(a), hb = __float2half_rn(b);
    h->x = ha; h->y = hb;
    l->x = __float2half_rn(a - __half2float(ha));
    l->y = __float2half_rn(b - __half2float(hb));
}

// copy rows x 128B into SW128-swizzled smem tile (byte pitch)
__device__ __forceinline__ void cp_rows(uint32_t dst, const char* src, long pitchB, int rows) {
    for (int idx = threadIdx.x; idx < rows * 8; idx += 256) {
        const int r = idx >> 3, cg = idx & 7;
        cp16(dst + SWZ(r * 128 + cg * 16), src + (long)r * pitchB + cg * 16);
    }
}

// ========== old 32x64-warp core (for qkv/proj, bf16 3-term) ==========
__device__ __forceinline__ void cp_chunk(uint32_t stb,
                                         const __nv_bfloat16* Ah, const __nv_bfloat16* Al,
                                         const __nv_bfloat16* Bh, const __nv_bfloat16* Bl,
                                         long pitch, long k0) {
    cp_rows(stb,         (const char*)(Ah + k0), pitch * 2, 128);
    cp_rows(stb + 16384, (const char*)(Al + k0), pitch * 2, 128);
    cp_rows(stb + 32768, (const char*)(Bh + k0), pitch * 2, 128);
    cp_rows(stb + 49152, (const char*)(Bl + k0), pitch * 2, 128);
}
__device__ __forceinline__ void mma_chunk(uint32_t sAh, uint32_t sAl, uint32_t sBh, uint32_t sBl,
                                          float (&acc)[2][8][4], int wm, int wn, int lane) {
    const int lr = lane & 15;
    const int lc = (lane >> 4) * 16;
    #pragma unroll
    for (int kk = 0; kk < 4; kk++) {
        const int kb = kk * 32;
        uint32_t ah[2][4], al[2][4];
        #pragma unroll
        for (int mt = 0; mt < 2; mt++) {
            const uint32_t off = SWZ((wm * 32 + mt * 16 + lr) * 128 + kb + lc);
            ldm4(ah[mt], sAh + off);
            ldm4(al[mt], sAl + off);
        }
        #pragma unroll
        for (int np = 0; np < 4; np++) {
            const uint32_t off = SWZ((wn * 64 + np * 16 + lr) * 128 + kb + lc);
            uint32_t bh[4], bl[4];
            ldm4(bh, sBh + off);
            ldm4(bl, sBl + off);
            uint32_t b0h[2] = {bh[0], bh[2]}, b1h[2] = {bh[1], bh[3]};
            uint32_t b0l[2] = {bl[0], bl[2]}, b1l[2] = {bl[1], bl[3]};
            #pragma unroll
            for (int mt = 0; mt < 2; mt++) {
                mma16816(acc[mt][np * 2],     ah[mt], b0h);
                mma16816(acc[mt][np * 2 + 1], ah[mt], b1h);
                mma16816(acc[mt][np * 2],     ah[mt], b0l);
                mma16816(acc[mt][np * 2 + 1], ah[mt], b1l);
                mma16816(acc[mt][np * 2],     al[mt], b0h);
                mma16816(acc[mt][np * 2 + 1], al[mt], b1h);
            }
        }
    }
}
__device__ __forceinline__ void hmma_pipeline(uint32_t sb,
        const __nv_bfloat16* Ah, const __nv_bfloat16* Al,
        const __nv_bfloat16* Bh, const __nv_bfloat16* Bl,
        long pitch, int nch, float (&acc)[2][8][4], int wm, int wn, int lane) {
    cp_chunk(sb, Ah, Al, Bh, Bl, pitch, 0);
    asm volatile("cp.async.commit_group;" ::: "memory");
    for (int ch = 0; ch < nch; ch++) {
        const uint32_t stb = sb + (ch & 1) * 65536;
        if (ch + 1 < nch) {
            cp_chunk(sb + ((ch + 1) & 1) * 65536, Ah, Al, Bh, Bl, pitch, (long)(ch + 1) * 64);
            asm volatile("cp.async.commit_group;" ::: "memory");
            asm volatile("cp.async.wait_group 1;" ::: "memory");
        } else {
            asm volatile("cp.async.wait_group 0;" ::: "memory");
        }
        __syncthreads();
        mma_chunk(stb, stb + 16384, stb + 32768, stb + 49152, acc, wm, wn, lane);
        __syncthreads();
    }
}

// ---------- GroupNorm ----------
__global__ void __launch_bounds__(256) gn_kernel(const float* __restrict__ x,
                                                 const float* __restrict__ w,
                                                 const float* __restrict__ bias) {
    const int b = blockIdx.x >> 5, g = blockIdx.x & 31;
    const float* xp = x   + (b * CH + g * CPG) * NPIX;
    float*       hp = g_h + (b * CH + g * CPG) * NPIX;
    const int NE = CPG * NPIX;
    float s = 0.f, ss = 0.f;
    const float4* x4 = (const float4*)xp;
    for (int i = threadIdx.x; i < NE / 4; i += 256) {
        float4 v = x4[i];
        s  += v.x + v.y + v.z + v.w;
        ss += v.x * v.x + v.y * v.y + v.z * v.z + v.w * v.w;
    }
    __shared__ float rs[32], rss[32];
    #pragma unroll
    for (int o = 16; o; o >>= 1) {
        s  += __shfl_xor_sync(~0u, s,  o);
        ss += __shfl_xor_sync(~0u, ss, o);
    }
    const int lane = threadIdx.x & 31, wid = threadIdx.x >> 5;
    if (lane == 0) { rs[wid] = s; rss[wid] = ss; }
    __syncthreads();
    if (wid == 0) {
        s  = (lane < 8) ? rs[lane]  : 0.f;
        ss = (lane < 8) ? rss[lane] : 0.f;
        #pragma unroll
        for (int o = 16; o; o >>= 1) {
            s  += __shfl_xor_sync(~0u, s,  o);
            ss += __shfl_xor_sync(~0u, ss, o);
        }
        if (lane == 0) { rs[0] = s; rss[0] = ss; }
    }
    __syncthreads();
    const float mu   = rs[0] / (float)NE;
    const float rstd = rsqrtf(rss[0] / (float)NE - mu * mu + 1e-5f);
    float4* h4 = (float4*)hp;
    for (int i = threadIdx.x; i < NE / 4; i += 256) {
        const int c = g * CPG + (i >> 10);
        const float wc = w[c] * rstd, bc = bias[c] - mu * wc;
        float4 v = x4[i];
        v.x = v.x * wc + bc; v.y = v.y * wc + bc; v.z = v.z * wc + bc; v.w = v.w * wc + bc;
        h4[i] = v;
    }
}

// ---------- h: [c][n] fp32 -> [n][c] hi/lo bf16 ----------
__global__ void __launch_bounds__(256) h_convert() {
    __shared__ float t[32][33];
    const int n0 = blockIdx.x * 32, c0 = blockIdx.y * 32, b = blockIdx.z;
    const float* src = g_h + ((size_t)b * CH + c0) * NPIX + n0;
    const int tx = threadIdx.x & 31, ty = threadIdx.x >> 5;
    #pragma unroll
    for (int j = 0; j < 4; j++)
        t[ty + 8 * j][tx] = src[(size_t)(ty + 8 * j) * NPIX + tx];
    __syncthreads();
    const size_t dbase = ((size_t)b * NPIX + n0) * CH + c0;
    #pragma unroll
    for (int j = 0; j < 4; j++) {
        float v = t[tx][ty + 8 * j];
        __nv_bfloat16 h = __float2bfloat16(v);
        g_hh[dbase + (size_t)(ty + 8 * j) * CH + tx] = h;
        g_hl[dbase + (size_t)(ty + 8 * j) * CH + tx] = __float2bfloat16(v - __bfloat162float(h));
    }
}

// ---------- weight split ----------
__global__ void __launch_bounds__(256) w_convert(const float* __restrict__ qkv_w,
                                                 const float* __restrict__ proj_w) {
    const int f4 = blockIdx.x * 256 + threadIdx.x;
    const float* src;
    __nv_bfloat16 *dh, *dl;
    size_t e;
    if (f4 < 49152) { src = qkv_w;  dh = g_wqh; dl = g_wql; e = (size_t)f4 * 4; }
    else            { src = proj_w; dh = g_wph; dl = g_wpl; e = (size_t)(f4 - 49152) * 4; }
    float4 v = *(const float4*)(src + e);
    __nv_bfloat162 h0, h1, l0, l1;
    split2(v.x, v.y, &h0, &l0);
    split2(v.z, v.w, &h1, &l1);
    *(__nv_bfloat162*)(dh + e)     = h0; *(__nv_bfloat162*)(dh + e + 2) = h1;
    *(__nv_bfloat162*)(dl + e)     = l0; *(__nv_bfloat162*)(dl + e + 2) = l1;
}

// ---------- QKV (old core; q,k -> [n][c] bf16 hi/lo, v -> [c][n] fp16 hi/lo) ----------
__global__ void __launch_bounds__(256, 1) qkv_hmma(const float* __restrict__ qkv_b) {
    extern __shared__ char smem[];
    const uint32_t sb = smem_u32(smem);
    const int tid = threadIdx.x, lane = tid & 31, wid = tid >> 5;
    const int wm = wid & 3, wn = wid >> 2;
    const int b = blockIdx.z, n0 = blockIdx.x * 128, o0 = blockIdx.y * 128;

    const __nv_bfloat16* Ah = g_wqh + (size_t)o0 * CH;
    const __nv_bfloat16* Al = g_wql + (size_t)o0 * CH;
    const __nv_bfloat16* Bh = g_hh + ((size_t)b * NPIX + n0) * CH;
    const __nv_bfloat16* Bl = g_hl + ((size_t)b * NPIX + n0) * CH;

    float acc[2][8][4] = {};
    hmma_pipeline(sb, Ah, Al, Bh, Bl, CH, 4, acc, wm, wn, lane);

    const int r0 = wm * 32 + (lane >> 2), c0 = wn * 64 + (lane & 3) * 2;
    #pragma unroll
    for (int mt = 0; mt < 2; mt++) {
        const float b0 = qkv_b[o0 + r0 + mt * 16];
        const float b1 = qkv_b[o0 + r0 + mt * 16 + 8];
        #pragma unroll
        for (int nt = 0; nt < 8; nt++) {
            acc[mt][nt][0] += b0; acc[mt][nt][1] += b0;
            acc[mt][nt][2] += b1; acc[mt][nt][3] += b1;
        }
    }

    const int sel = blockIdx.y >> 1;   // 0=q, 1=k, 2=v
    if (sel == 2) {
        __half* vh = g_v16h + ((size_t)b * CH + (o0 - 512)) * NPIX + n0;
        __half* vl = g_v16l + ((size_t)b * CH + (o0 - 512)) * NPIX + n0;
        #pragma unroll
        for (int mt = 0; mt < 2; mt++)
            #pragma unroll
            for (int nt = 0; nt < 8; nt++) {
                const int rr = r0 + mt * 16, cc = c0 + nt * 8;
                __half2 h, l;
                split2h(acc[mt][nt][0], acc[mt][nt][1], &h, &l);
                *(__half2*)(vh + (size_t)rr * NPIX + cc) = h;
                *(__half2*)(vl + (size_t)rr * NPIX + cc) = l;
                split2h(acc[mt][nt][2], acc[mt][nt][3], &h, &l);
                *(__half2*)(vh + (size_t)(rr + 8) * NPIX + cc) = h;
                *(__half2*)(vl + (size_t)(rr + 8) * NPIX + cc) = l;
            }
    } else {
        float* st = (float*)smem;   // [c 128][n 132]
        #pragma unroll
        for (int mt = 0; mt < 2; mt++)
            #pragma unroll
            for (int nt = 0; nt < 8; nt++) {
                const int rr = r0 + mt * 16, cc = c0 + nt * 8;
                st[(cc)     * 132 + rr]     = acc[mt][nt][0];
                st[(cc + 1) * 132 + rr]     = acc[mt][nt][1];
                st[(cc)     * 132 + rr + 8] = acc[mt][nt][2];
                st[(cc + 1) * 132 + rr + 8] = acc[mt][nt][3];
            }
        __syncthreads();
        __nv_bfloat16* dh = (sel ? g_kh : g_qh) + ((size_t)b * NPIX + n0) * CH + (o0 - sel * 256);
        __nv_bfloat16* dl = (sel ? g_kl : g_ql) + ((size_t)b * NPIX + n0) * CH + (o0 - sel * 256);
        const int o4 = lane * 4, nb = tid >> 5;
        #pragma unroll
        for (int j = 0; j < 16; j++) {
            const int n = nb + 8 * j;
            float4 v = *(float4*)(st + n * 132 + o4);
            __nv_bfloat162 h0, h1, l0, l1;
            split2(v.x, v.y, &h0, &l0);
            split2(v.z, v.w, &h1, &l1);
            *(__nv_bfloat162*)(dh + (size_t)n * CH + o4)     = h0;
            *(__nv_bfloat162*)(dh + (size_t)n * CH + o4 + 2) = h1;
            *(__nv_bfloat162*)(dl + (size_t)n * CH + o4)     = l0;
            *(__nv_bfloat162*)(dl + (size_t)n * CH + o4 + 2) = l1;
        }
    }
}

// ---------- S = Q K^T (CTA 256x128, warp 64x64, bf16 3-term) ----------
// stage: Ah 32K @0 | Al 32K @32768 | Bh 16K @65536 | Bl 16K @81920 = 96K; x2 = 192K
__global__ void __launch_bounds__(256, 1) s_gemm_kernel() {
    extern __shared__ char smem[];
    const uint32_t sb = smem_u32(smem);
    const int tid = threadIdx.x, lane = tid & 31, wid = tid >> 5;
    const int wm = wid & 3, wn = wid >> 2;   // 4 x 2 warps
    const int b = blockIdx.z, i0 = blockIdx.y * 256, j0 = blockIdx.x * 128;

    const char* Ah = (const char*)(g_qh + ((size_t)b * NPIX + i0) * CH);
    const char* Al = (const char*)(g_ql + ((size_t)b * NPIX + i0) * CH);
    const char* Bh = (const char*)(g_kh + ((size_t)b * NPIX + j0) * CH);
    const char* Bl = (const char*)(g_kl + ((size_t)b * NPIX + j0) * CH);
    const long pB = CH * 2;

    float acc[4][8][4] = {};
    const int lr = lane & 15, lc = (lane >> 4) * 16;

    {   // prefetch chunk 0
        cp_rows(sb,         Ah, pB, 256);
        cp_rows(sb + 32768, Al, pB, 256);
        cp_rows(sb + 65536, Bh, pB, 128);
        cp_rows(sb + 81920, Bl, pB, 128);
        asm volatile("cp.async.commit_group;" ::: "memory");
    }
    for (int ch = 0; ch < 4; ch++) {
        const uint32_t stb = sb + (ch & 1) * 98304;
        if (ch + 1 < 4) {
            const uint32_t nstb = sb + ((ch + 1) & 1) * 98304;
            const long k0 = (long)(ch + 1) * 128;   // bytes
            cp_rows(nstb,         Ah + k0, pB, 256);
            cp_rows(nstb + 32768, Al + k0, pB, 256);
            cp_rows(nstb + 65536, Bh + k0, pB, 128);
            cp_rows(nstb + 81920, Bl + k0, pB, 128);
            asm volatile("cp.async.commit_group;" ::: "memory");
            asm volatile("cp.async.wait_group 1;" ::: "memory");
        } else {
            asm volatile("cp.async.wait_group 0;" ::: "memory");
        }
        __syncthreads();
        #pragma unroll
        for (int kk = 0; kk < 4; kk++) {
            const int kb = kk * 32;
            uint32_t ah[4][4], al[4][4];
            #pragma unroll
            for (int mt = 0; mt < 4; mt++) {
                const uint32_t off = SWZ((wm * 64 + mt * 16 + lr) * 128 + kb + lc);
                ldm4(ah[mt], stb + off);
                ldm4(al[mt], stb + 32768 + off);
            }
            #pragma unroll
            for (int np = 0; np < 4; np++) {
                const uint32_t off = SWZ((wn * 64 + np * 16 + lr) * 128 + kb + lc);
                uint32_t bh[4], bl[4];
                ldm4(bh, stb + 65536 + off);
                ldm4(bl, stb + 81920 + off);
                uint32_t b0h[2] = {bh[0], bh[2]}, b1h[2] = {bh[1], bh[3]};
                uint32_t b0l[2] = {bl[0], bl[2]}, b1l[2] = {bl[1], bl[3]};
                #pragma unroll
                for (int mt = 0; mt < 4; mt++) {
                    mma16816(acc[mt][np * 2],     ah[mt], b0h);
                    mma16816(acc[mt][np * 2 + 1], ah[mt], b1h);
                    mma16816(acc[mt][np * 2],     ah[mt], b0l);
                    mma16816(acc[mt][np * 2 + 1], ah[mt], b1l);
                    mma16816(acc[mt][np * 2],     al[mt], b0h);
                    mma16816(acc[mt][np * 2 + 1], al[mt], b1h);
                }
            }
        }
        __syncthreads();
    }

    float* Sb = g_S + ((size_t)b * NPIX + i0) * NPIX + j0;
    const int r0 = wm * 64 + (lane >> 2), c0 = wn * 64 + (lane & 3) * 2;
    #pragma unroll
    for (int mt = 0; mt < 4; mt++)
        #pragma unroll
        for (int nt = 0; nt < 8; nt++) {
            float* p = Sb + (size_t)(r0 + mt * 16) * NPIX + c0 + nt * 8;
            *(float2*)p = make_float2(acc[mt][nt][0], acc[mt][nt][1]);
            *(float2*)(p + (size_t)8 * NPIX) = make_float2(acc[mt][nt][2], acc[mt][nt][3]);
        }
}

// ---------- softmax rows -> P fp16 ----------
__global__ void __launch_bounds__(256) softmax_kernel() {
    const size_t row = blockIdx.x;
    const float4* s4 = (const float4*)(g_S + row * NPIX);
    const int tid = threadIdx.x, lane = tid & 31, wid = tid >> 5;
    __shared__ float rmax[8], rsum[8];
    float4 v[4];
    float mx = -1e30f;
    #pragma unroll
    for (int k = 0; k < 4; k++) {
        float4 t = s4[tid + 256 * k];
        t.x *= SCALE; t.y *= SCALE; t.z *= SCALE; t.w *= SCALE;
        v[k] = t;
        mx = fmaxf(mx, fmaxf(fmaxf(t.x, t.y), fmaxf(t.z, t.w)));
    }
    #pragma unroll
    for (int o = 16; o; o >>= 1) mx = fmaxf(mx, __shfl_xor_sync(~0u, mx, o));
    if (lane == 0) rmax[wid] = mx;
    __syncthreads();
    mx = rmax[0];
    #pragma unroll
    for (int i = 1; i < 8; i++) mx = fmaxf(mx, rmax[i]);
    float sum = 0.f;
    #pragma unroll
    for (int k = 0; k < 4; k++) {
        v[k].x = __expf(v[k].x - mx); v[k].y = __expf(v[k].y - mx);
        v[k].z = __expf(v[k].z - mx); v[k].w = __expf(v[k].w - mx);
        sum += v[k].x + v[k].y + v[k].z + v[k].w;
    }
    #pragma unroll
    for (int o = 16; o; o >>= 1) sum += __shfl_xor_sync(~0u, sum, o);
    if (lane == 0) rsum[wid] = sum;
    __syncthreads();
    sum = rsum[0]+rsum[1]+rsum[2]+rsum[3]+rsum[4]+rsum[5]+rsum[6]+rsum[7];
    const float inv = 1.f / sum;
    __half* ph = g_p + row * NPIX;
    #pragma unroll
    for (int k = 0; k < 4; k++) {
        const int e0 = (tid + 256 * k) * 4;
        __half2 h0, h1;
        h0.x = __float2half_rn(v[k].x * inv); h0.y = __float2half_rn(v[k].y * inv);
        h1.x = __float2half_rn(v[k].z * inv); h1.y = __float2half_rn(v[k].w * inv);
        *(__half2*)(ph + e0)     = h0;
        *(__half2*)(ph + e0 + 2) = h1;
    }
}

// ---------- O = P V (CTA 128x256, warp 64x64, fp16, 2-term) ----------
// stage: P 16K @0 | Vh 32K @16384 | Vl 32K @49152 = 80K; x2 = 160K
__global__ void __launch_bounds__(256, 1) pv_gemm_kernel() {
    extern __shared__ char smem[];
    const uint32_t sb = smem_u32(smem);
    const int tid = threadIdx.x, lane = tid & 31, wid = tid >> 5;
    const int wm = wid & 1, wn = wid >> 1;   // 2 x 4 warps
    const int b = blockIdx.x & 3, i0 = (blockIdx.x >> 2) * 128;

    const char* Ap = (const char*)(g_p + ((size_t)b * NPIX + i0) * NPIX);
    const char* Bh = (const char*)(g_v16h + (size_t)b * CH * NPIX);
    const char* Bl = (const char*)(g_v16l + (size_t)b * CH * NPIX);
    const long pB = NPIX * 2;

    float acc[4][8][4] = {};
    const int lr = lane & 15, lc = (lane >> 4) * 16;

    cp_rows(sb,         Ap, pB, 128);
    cp_rows(sb + 16384, Bh, pB, 256);
    cp_rows(sb + 49152, Bl, pB, 256);
    asm volatile("cp.async.commit_group;" ::: "memory");

    for (int ch = 0; ch < 64; ch++) {
        const uint32_t stb = sb + (ch & 1) * 81920;
        if (ch + 1 < 64) {
            const uint32_t nstb = sb + ((ch + 1) & 1) * 81920;
            const long k0 = (long)(ch + 1) * 128;   // bytes
            cp_rows(nstb,         Ap + k0, pB, 128);
            cp_rows(nstb + 16384, Bh + k0, pB, 256);
            cp_rows(nstb + 49152, Bl + k0, pB, 256);
            asm volatile("cp.async.commit_group;" ::: "memory");
            asm volatile("cp.async.wait_group 1;" ::: "memory");
        } else {
            asm volatile("cp.async.wait_group 0;" ::: "memory");
        }
        __syncthreads();
        #pragma unroll
        for (int kk = 0; kk < 4; kk++) {
            const int kb = kk * 32;
            uint32_t a[4][4];
            #pragma unroll
            for (int mt = 0; mt < 4; mt++) {
                const uint32_t off = SWZ((wm * 64 + mt * 16 + lr) * 128 + kb + lc);
                ldm4(a[mt], stb + off);
            }
            #pragma unroll
            for (int np = 0; np < 4; np++) {
                const uint32_t off = SWZ((wn * 64 + np * 16 + lr) * 128 + kb + lc);
                uint32_t bh[4], bl[4];
                ldm4(bh, stb + 16384 + off);
                ldm4(bl, stb + 49152 + off);
                uint32_t b0h[2] = {bh[0], bh[2]}, b1h[2] = {bh[1], bh[3]};
                uint32_t b0l[2] = {bl[0], bl[2]}, b1l[2] = {bl[1], bl[3]};
                #pragma unroll
                for (int mt = 0; mt < 4; mt++) {
                    mma16816h(acc[mt][np * 2],     a[mt], b0h);
                    mma16816h(acc[mt][np * 2 + 1], a[mt], b1h);
                    mma16816h(acc[mt][np * 2],     a[mt], b0l);
                    mma16816h(acc[mt][np * 2 + 1], a[mt], b1l);
                }
            }
        }
        __syncthreads();
    }

    // acc rows = pixel, cols = channel -> O^T [n][c] hi/lo bf16
    __nv_bfloat16* oh = g_oh + ((size_t)b * NPIX + i0) * CH;
    __nv_bfloat16* ol = g_ol + ((size_t)b * NPIX + i0) * CH;
    const int r0 = wm * 64 + (lane >> 2), c0 = wn * 64 + (lane & 3) * 2;
    #pragma unroll
    for (int mt = 0; mt < 4; mt++)
        #pragma unroll
        for (int nt = 0; nt < 8; nt++) {
            const int rr = r0 + mt * 16, cc = c0 + nt * 8;
            __nv_bfloat162 h, l;
            split2(acc[mt][nt][0], acc[mt][nt][1], &h, &l);
            *(__nv_bfloat162*)(oh + (size_t)rr * CH + cc) = h;
            *(__nv_bfloat162*)(ol + (size_t)rr * CH + cc) = l;
            split2(acc[mt][nt][2], acc[mt][nt][3], &h, &l);
            *(__nv_bfloat162*)(oh + (size_t)(rr + 8) * CH + cc) = h;
            *(__nv_bfloat162*)(ol + (size_t)(rr + 8) * CH + cc) = l;
        }
}

// ---------- out = proj_w * O + proj_b + x ----------
__global__ void __launch_bounds__(256, 1) proj_hmma(const float* __restrict__ proj_b,
                                                    const float* __restrict__ x,
                                                    float* __restrict__ out) {
    extern __shared__ char smem[];
    const uint32_t sb = smem_u32(smem);
    const int tid = threadIdx.x, lane = tid & 31, wid = tid >> 5;
    const int wm = wid & 3, wn = wid >> 2;
    const int b = blockIdx.z, n0 = blockIdx.x * 128, o0 = blockIdx.y * 128;

    const __nv_bfloat16* Ah = g_wph + (size_t)o0 * CH;
    const __nv_bfloat16* Al = g_wpl + (size_t)o0 * CH;
    const __nv_bfloat16* Bh = g_oh + ((size_t)b * NPIX + n0) * CH;
    const __nv_bfloat16* Bl = g_ol + ((size_t)b * NPIX + n0) * CH;

    float acc[2][8][4] = {};
    hmma_pipeline(sb, Ah, Al, Bh, Bl, CH, 4, acc, wm, wn, lane);

    const int r0 = wm * 32 + (lane >> 2), c0 = wn * 64 + (lane & 3) * 2;
    #pragma unroll
    for (int mt = 0; mt < 2; mt++) {
        const int r  = o0 + r0 + mt * 16;
        const float b0 = proj_b[r], b1 = proj_b[r + 8];
        #pragma unroll
        for (int nt = 0; nt < 8; nt++) {
            const size_t idx0 = ((size_t)b * CH + r) * NPIX + n0 + c0 + nt * 8;
            const size_t idx1 = idx0 + (size_t)8 * NPIX;
            float2 x0 = *(const float2*)(x + idx0);
            float2 x1 = *(const float2*)(x + idx1);
            *(float2*)(out + idx0) = make_float2(acc[mt][nt][0] + b0 + x0.x,
                                                 acc[mt][nt][1] + b0 + x0.y);
            *(float2*)(out + idx1) = make_float2(acc[mt][nt][2] + b1 + x1.x,
                                                 acc[mt][nt][3] + b1 + x1.y);
        }
    }
}

// ---------- launch ----------
extern "C" void kernel_launch(void* const* d_in, const int* in_sizes, int n_in,
                              void* d_out, int out_size) {
    const float* x      = (const float*)d_in[0];
    const float* gn_w   = (const float*)d_in[1];
    const float* gn_b   = (const float*)d_in[2];
    const float* qkv_w  = (const float*)d_in[3];
    const float* qkv_b  = (const float*)d_in[4];
    const float* proj_w = (const float*)d_in[5];
    const float* proj_b = (const float*)d_in[6];
    float* out = (float*)d_out;

    cudaFuncSetAttribute(qkv_hmma,      cudaFuncAttributeMaxDynamicSharedMemorySize, 131072);
    cudaFuncSetAttribute(proj_hmma,     cudaFuncAttributeMaxDynamicSharedMemorySize, 131072);
    cudaFuncSetAttribute(s_gemm_kernel, cudaFuncAttributeMaxDynamicSharedMemorySize, 196608);
    cudaFuncSetAttribute(pv_gemm_kernel,cudaFuncAttributeMaxDynamicSharedMemorySize, 163840);

    w_convert<<<256, 256>>>(qkv_w, proj_w);
    gn_kernel<<<BATCH * 32, 256>>>(x, gn_w, gn_b);
    {
        dim3 g(NPIX / 32, CH / 32, BATCH);
        h_convert<<<g, 256>>>();
    }
    {
        dim3 g(NPIX / 128, 6, BATCH);
        qkv_hmma<<<g, 256, 131072>>>(qkv_b);
    }
    {
        dim3 g(NPIX / 128, NPIX / 256, BATCH);
        s_gemm_kernel<<<g, 256, 196608>>>();
    }
    softmax_kernel<<<BATCH * NPIX, 256>>>();
    pv_gemm_kernel<<<(NPIX / 128) * BATCH, 256, 163840>>>();
    {
        dim3 g(NPIX / 128, 2, BATCH);
        proj_hmma<<<g, 256, 131072>>>(proj_b, x, out);
    }
}